// round 5
// baseline (speedup 1.0000x reference)
#include <cuda_runtime.h>
#include <cstdint>

#define C_DIM   1024
#define NSEQ    2048
#define NHEADS  16
#define HDIM    64
#define BATCH   2
#define ROWS    (BATCH * NSEQ)       // 4096
#define ATT_SCALE 0.125f             // 1/sqrt(64)

// Scratch (no allocations allowed in kernel_launch)
__device__ float g_qkv[ROWS * 3 * C_DIM];   // [4096, 3072]
__device__ float g_att[ROWS * C_DIM];       // [4096, 1024]

// ===========================================================================
// tf32 helpers (arch-independent PTX)
// ===========================================================================
__device__ __forceinline__ uint32_t f2tf32(float x) {
    uint32_t r;
    asm("cvt.rna.tf32.f32 %0, %1;" : "=r"(r) : "f"(x));
    return r;
}

// D += A @ B  for one m16n8k8 tf32 tile.
// k-slots are PERMUTED per 8-octet: slot (c, c+4) -> physical col (2c, 2c+1).
// Valid because mma sums over k and A/B use the same permutation.
// So: a0=A[r][2c] a1=A[r+8][2c] a2=A[r][2c+1] a3=A[r+8][2c+1]
//     b0=B[2c][n] b1=B[2c+1][n]
// Output unchanged: d0=C[r][2c'] d1=C[r][2c'+1] d2/d3 rows +8 (c' = lane quad).
__device__ __forceinline__ void mma_tf32(float* d, const uint32_t* a, const uint32_t* b) {
    asm volatile(
        "mma.sync.aligned.m16n8k8.row.col.f32.tf32.tf32.f32 "
        "{%0,%1,%2,%3}, {%4,%5,%6,%7}, {%8,%9}, {%0,%1,%2,%3};"
        : "+f"(d[0]), "+f"(d[1]), "+f"(d[2]), "+f"(d[3])
        : "r"(a[0]), "r"(a[1]), "r"(a[2]), "r"(a[3]), "r"(b[0]), "r"(b[1]));
}

// ===========================================================================
// tf32 mma.sync NT GEMM:  C[M,Nt] = A[M,K] @ W[Nt,K]^T + bias[Nt]
// 128x128 tile, BK=32, 256 threads (8 warps, 64x32 each), 2 CTAs/SM.
// Pitch 40 (== 8 mod 32): LDS.64 fragment loads are bank-conflict-free.
// Frag loads via k-perm: A = 2x LDS.64, B = 1x LDS.64.
// ===========================================================================
#define GP 40
#define GSTAGE_F (2 * 128 * GP)          // A + B per stage (floats)
#define GEMM_SMEM (2 * GSTAGE_F * 4)     // 81920 B

__global__ __launch_bounds__(256, 2)
void gemm_mma_tf32(const float* __restrict__ A, const float* __restrict__ W,
                   const float* __restrict__ bias, float* __restrict__ Cout,
                   int M, int Nt, int K)
{
    extern __shared__ float smf[];
    const int t      = threadIdx.x;
    const int lane   = t & 31;
    const int r      = lane >> 2;
    const int cq     = lane & 3;
    const int wid    = t >> 5;
    const int warp_m = wid & 1;     // 2 warps over M (64 rows each)
    const int warp_n = wid >> 1;    // 4 warps over N (32 cols each)
    const int m0 = blockIdx.y << 7;
    const int n0 = blockIdx.x << 7;

    float acc[4][4][4];
#pragma unroll
    for (int i = 0; i < 4; i++)
#pragma unroll
        for (int j = 0; j < 4; j++)
#pragma unroll
            for (int e = 0; e < 4; e++) acc[i][j][e] = 0.f;

    const int nch = K / 32;
    const int grow = t >> 3;              // 0..31 (×4 via p)
    const int gc4  = (t & 7) << 2;        // 0..28

    float4 ra[4], rw[4];

#define LOAD_GMEM(cidx)                                                        \
    {                                                                          \
        const float* Ap = A + (size_t)m0 * K + (cidx) * 32;                    \
        const float* Wp = W + (size_t)n0 * K + (cidx) * 32;                    \
        _Pragma("unroll")                                                      \
        for (int p = 0; p < 4; p++) {                                          \
            int row = grow + p * 32;                                           \
            ra[p] = *(const float4*)(Ap + (size_t)row * K + gc4);              \
            rw[p] = *(const float4*)(Wp + (size_t)row * K + gc4);              \
        }                                                                      \
    }

#define STORE_STAGE(s)                                                         \
    {                                                                          \
        float* As = smf + (s) * GSTAGE_F;                                      \
        float* Bs = As + 128 * GP;                                             \
        _Pragma("unroll")                                                      \
        for (int p = 0; p < 4; p++) {                                          \
            int row = grow + p * 32;                                           \
            uint4 ua = make_uint4(f2tf32(ra[p].x), f2tf32(ra[p].y),            \
                                  f2tf32(ra[p].z), f2tf32(ra[p].w));           \
            uint4 uw = make_uint4(f2tf32(rw[p].x), f2tf32(rw[p].y),            \
                                  f2tf32(rw[p].z), f2tf32(rw[p].w));           \
            *(uint4*)&As[row * GP + gc4] = ua;                                 \
            *(uint4*)&Bs[row * GP + gc4] = uw;                                 \
        }                                                                      \
    }

    LOAD_GMEM(0);
    STORE_STAGE(0);
    __syncthreads();

    for (int c = 0; c < nch; c++) {
        const int s = c & 1;
        if (c + 1 < nch) LOAD_GMEM(c + 1);

        const float* As = smf + s * GSTAGE_F;
        const float* Bs = As + 128 * GP;
#pragma unroll
        for (int ks = 0; ks < 4; ks++) {
            uint32_t afr[4][4], bfr[4][2];
#pragma unroll
            for (int mt = 0; mt < 4; mt++) {
                const float* Ab = As + (warp_m * 64 + mt * 16) * GP + ks * 8 + 2 * cq;
                float2 lo = *(const float2*)&Ab[r * GP];
                float2 hi = *(const float2*)&Ab[(r + 8) * GP];
                afr[mt][0] = __float_as_uint(lo.x);
                afr[mt][1] = __float_as_uint(hi.x);
                afr[mt][2] = __float_as_uint(lo.y);
                afr[mt][3] = __float_as_uint(hi.y);
            }
#pragma unroll
            for (int nt = 0; nt < 4; nt++) {
                float2 bv = *(const float2*)&Bs[(warp_n * 32 + nt * 8 + r) * GP + ks * 8 + 2 * cq];
                bfr[nt][0] = __float_as_uint(bv.x);
                bfr[nt][1] = __float_as_uint(bv.y);
            }
#pragma unroll
            for (int mt = 0; mt < 4; mt++)
#pragma unroll
                for (int nt = 0; nt < 4; nt++)
                    mma_tf32(acc[mt][nt], afr[mt], bfr[nt]);
        }

        if (c + 1 < nch) STORE_STAGE(s ^ 1);   // opposite buffer: safe pre-sync
        __syncthreads();
    }

    // Epilogue: direct stores with bias
    const int c2 = cq << 1;
#pragma unroll
    for (int nt = 0; nt < 4; nt++) {
        const int gn = n0 + warp_n * 32 + nt * 8 + c2;
        const float b0 = bias[gn], b1 = bias[gn + 1];
#pragma unroll
        for (int mt = 0; mt < 4; mt++) {
            const int gm = m0 + warp_m * 64 + mt * 16 + r;
            float2 v0, v1;
            v0.x = acc[mt][nt][0] + b0; v0.y = acc[mt][nt][1] + b1;
            v1.x = acc[mt][nt][2] + b0; v1.y = acc[mt][nt][3] + b1;
            *(float2*)&Cout[(size_t)gm * Nt + gn]       = v0;
            *(float2*)&Cout[(size_t)(gm + 8) * Nt + gn] = v1;
        }
    }
#undef LOAD_GMEM
#undef STORE_STAGE
}

// ===========================================================================
// Flash attention with tf32 mma.sync + k-perm register reuse.
// Block: 256 queries x one (b,h). 512 threads = 16 warps; warp owns 16 rows.
// KEY TRICK: with the k-perm on PV's key octets, the S-mma output registers
// at lane (r,cq) -- S cols 2cq,2cq+1 -- ARE the PV A-fragment slots (cq,cq+4).
// P never touches smem. No Ps buffer, no extra syncs.
// smem (floats, pitch 72 == 8 mod 32 -> conflict-free LDS.64 frags):
//   Qs[256][72] | K0[64][72] | V0[64][72] | K1[64][72] | V1[64][72]
// ===========================================================================
#define AQ      256
#define AP      72
#define OFF_K0  (AQ * AP)                    // 18432
#define OFF_V0  (OFF_K0 + 64 * AP)           // 23040
#define OFF_K1  (OFF_V0 + 64 * AP)           // 27648
#define OFF_V1  (OFF_K1 + 64 * AP)           // 32256
#define ATTN_SMEM ((OFF_V1 + 64 * AP) * 4)   // 147456 B

__global__ __launch_bounds__(512)
void attn_mma(const float* __restrict__ qkv, float* __restrict__ out)
{
    extern __shared__ float sm[];
    const int t    = threadIdx.x;
    const int lane = t & 31;
    const int wid  = t >> 5;
    const int r    = lane >> 2;
    const int cq   = lane & 3;
    const int q0   = blockIdx.x * AQ;
    const int b    = blockIdx.y >> 4;
    const int h    = blockIdx.y & 15;
    const int rs   = 3 * C_DIM;

    const float* qb = qkv + ((size_t)(b * NSEQ + q0) * 3) * C_DIM + h * HDIM;
    const float* kb = qkv + ((size_t)(b * NSEQ) * 3 + 1) * C_DIM + h * HDIM;
    const float* vb = qkv + ((size_t)(b * NSEQ) * 3 + 2) * C_DIM + h * HDIM;

    // ---- stage Q (tf32) ----
#pragma unroll
    for (int p = 0; p < 8; p++) {
        int fi  = t + 512 * p;
        int row = fi >> 4;
        int d4  = (fi & 15) << 2;
        float4 v = *(const float4*)(qb + (size_t)row * rs + d4);
        uint4 u = make_uint4(f2tf32(v.x), f2tf32(v.y), f2tf32(v.z), f2tf32(v.w));
        *(uint4*)&sm[row * AP + d4] = u;
    }

    // K/V staging index (2 float4 each per thread)
    const int krow0 = t >> 4;              // 0..31
    const int krow1 = krow0 + 32;
    const int kd4   = (t & 15) << 2;

    // ---- stage K/V tile 0 ----
    {
        float4 k0 = *(const float4*)(kb + (size_t)krow0 * rs + kd4);
        float4 k1 = *(const float4*)(kb + (size_t)krow1 * rs + kd4);
        float4 v0 = *(const float4*)(vb + (size_t)krow0 * rs + kd4);
        float4 v1 = *(const float4*)(vb + (size_t)krow1 * rs + kd4);
        *(uint4*)&sm[OFF_K0 + krow0 * AP + kd4] =
            make_uint4(f2tf32(k0.x), f2tf32(k0.y), f2tf32(k0.z), f2tf32(k0.w));
        *(uint4*)&sm[OFF_K0 + krow1 * AP + kd4] =
            make_uint4(f2tf32(k1.x), f2tf32(k1.y), f2tf32(k1.z), f2tf32(k1.w));
        *(uint4*)&sm[OFF_V0 + krow0 * AP + kd4] =
            make_uint4(f2tf32(v0.x), f2tf32(v0.y), f2tf32(v0.z), f2tf32(v0.w));
        *(uint4*)&sm[OFF_V0 + krow1 * AP + kd4] =
            make_uint4(f2tf32(v1.x), f2tf32(v1.y), f2tf32(v1.z), f2tf32(v1.w));
    }
    __syncthreads();

    float o_[8][4];
#pragma unroll
    for (int nt = 0; nt < 8; nt++)
#pragma unroll
        for (int e = 0; e < 4; e++) o_[nt][e] = 0.f;
    float m0r = -1e30f, m1r = -1e30f, l0r = 0.f, l1r = 0.f;

    const int wrow = wid * 16;   // warp's query-row base within block

    for (int kt = 0; kt < NSEQ / 64; kt++) {
        const int s = kt & 1;
        const int koff = s ? OFF_K1 : OFF_K0;
        const int voff = s ? OFF_V1 : OFF_V0;

        // ---- S = Q @ K^T (warp: 16 rows x 64 cols), LDS.64 frags ----
        float s_[8][4];
#pragma unroll
        for (int nt = 0; nt < 8; nt++)
#pragma unroll
            for (int e = 0; e < 4; e++) s_[nt][e] = 0.f;

#pragma unroll
        for (int ks = 0; ks < 8; ks++) {
            uint32_t a[4];
            const float* Qb = &sm[wrow * AP + ks * 8 + 2 * cq];
            float2 qlo = *(const float2*)&Qb[r * AP];
            float2 qhi = *(const float2*)&Qb[(r + 8) * AP];
            a[0] = __float_as_uint(qlo.x);
            a[1] = __float_as_uint(qhi.x);
            a[2] = __float_as_uint(qlo.y);
            a[3] = __float_as_uint(qhi.y);
#pragma unroll
            for (int nt = 0; nt < 8; nt++) {
                float2 kv = *(const float2*)&sm[koff + (nt * 8 + r) * AP + ks * 8 + 2 * cq];
                uint32_t bf[2];
                bf[0] = __float_as_uint(kv.x);
                bf[1] = __float_as_uint(kv.y);
                mma_tf32(s_[nt], a, bf);
            }
        }

        // ---- prefetch next K/V tile (hidden behind softmax + PV) ----
        float4 pk0, pk1, pv0, pv1;
        if (kt + 1 < NSEQ / 64) {
            const float* kn = kb + (size_t)((kt + 1) * 64) * rs;
            const float* vn = vb + (size_t)((kt + 1) * 64) * rs;
            pk0 = *(const float4*)(kn + (size_t)krow0 * rs + kd4);
            pk1 = *(const float4*)(kn + (size_t)krow1 * rs + kd4);
            pv0 = *(const float4*)(vn + (size_t)krow0 * rs + kd4);
            pv1 = *(const float4*)(vn + (size_t)krow1 * rs + kd4);
        }

        // ---- online softmax (rows r and r+8; reduce over c-quad) ----
        float ml0 = -1e30f, ml1 = -1e30f;
#pragma unroll
        for (int nt = 0; nt < 8; nt++) {
            s_[nt][0] *= ATT_SCALE; s_[nt][1] *= ATT_SCALE;
            s_[nt][2] *= ATT_SCALE; s_[nt][3] *= ATT_SCALE;
            ml0 = fmaxf(ml0, fmaxf(s_[nt][0], s_[nt][1]));
            ml1 = fmaxf(ml1, fmaxf(s_[nt][2], s_[nt][3]));
        }
        ml0 = fmaxf(ml0, __shfl_xor_sync(0xffffffffu, ml0, 1));
        ml0 = fmaxf(ml0, __shfl_xor_sync(0xffffffffu, ml0, 2));
        ml1 = fmaxf(ml1, __shfl_xor_sync(0xffffffffu, ml1, 1));
        ml1 = fmaxf(ml1, __shfl_xor_sync(0xffffffffu, ml1, 2));

        float mn0 = fmaxf(m0r, ml0), mn1 = fmaxf(m1r, ml1);
        float cr0 = __expf(m0r - mn0), cr1 = __expf(m1r - mn1);
        m0r = mn0; m1r = mn1;

        float rs0 = 0.f, rs1 = 0.f;
#pragma unroll
        for (int nt = 0; nt < 8; nt++) {
            s_[nt][0] = __expf(s_[nt][0] - mn0);
            s_[nt][1] = __expf(s_[nt][1] - mn0);
            s_[nt][2] = __expf(s_[nt][2] - mn1);
            s_[nt][3] = __expf(s_[nt][3] - mn1);
            rs0 += s_[nt][0] + s_[nt][1];
            rs1 += s_[nt][2] + s_[nt][3];
        }
        rs0 += __shfl_xor_sync(0xffffffffu, rs0, 1);
        rs0 += __shfl_xor_sync(0xffffffffu, rs0, 2);
        rs1 += __shfl_xor_sync(0xffffffffu, rs1, 1);
        rs1 += __shfl_xor_sync(0xffffffffu, rs1, 2);
        l0r = l0r * cr0 + rs0;
        l1r = l1r * cr1 + rs1;

#pragma unroll
        for (int nt = 0; nt < 8; nt++) {
            o_[nt][0] *= cr0; o_[nt][1] *= cr0;
            o_[nt][2] *= cr1; o_[nt][3] *= cr1;
        }

        // ---- O += P @ V : P comes straight from s_ registers (k-perm) ----
        // PV k-octet ks == S n-tile ks. Lane (r,cq) S-output cols 2cq,2cq+1
        // are exactly PV a-slots (cq, cq+4):
        //   a0 = P[r][ks*8+2cq]   = s_[ks][0]
        //   a1 = P[r+8][ks*8+2cq] = s_[ks][2]
        //   a2 = P[r][ks*8+2cq+1] = s_[ks][1]
        //   a3 = P[r+8][ks*8+2cq+1] = s_[ks][3]
        // V b-frags: physical key rows ks*8+2cq, ks*8+2cq+1 at col nt*8+r.
#pragma unroll
        for (int ks = 0; ks < 8; ks++) {
            uint32_t a[4];
            a[0] = f2tf32(s_[ks][0]);
            a[1] = f2tf32(s_[ks][2]);
            a[2] = f2tf32(s_[ks][1]);
            a[3] = f2tf32(s_[ks][3]);
            const float* Vb = &sm[voff + (ks * 8 + 2 * cq) * AP + r];
#pragma unroll
            for (int nt = 0; nt < 8; nt++) {
                uint32_t bf[2];
                bf[0] = __float_as_uint(Vb[nt * 8]);
                bf[1] = __float_as_uint(Vb[nt * 8 + AP]);
                mma_tf32(o_[nt], a, bf);
            }
        }

        // ---- stage next tile into opposite buffer, then one barrier ----
        if (kt + 1 < NSEQ / 64) {
            const int nk = s ? OFF_K0 : OFF_K1;
            const int nv = s ? OFF_V0 : OFF_V1;
            *(uint4*)&sm[nk + krow0 * AP + kd4] =
                make_uint4(f2tf32(pk0.x), f2tf32(pk0.y), f2tf32(pk0.z), f2tf32(pk0.w));
            *(uint4*)&sm[nk + krow1 * AP + kd4] =
                make_uint4(f2tf32(pk1.x), f2tf32(pk1.y), f2tf32(pk1.z), f2tf32(pk1.w));
            *(uint4*)&sm[nv + krow0 * AP + kd4] =
                make_uint4(f2tf32(pv0.x), f2tf32(pv0.y), f2tf32(pv0.z), f2tf32(pv0.w));
            *(uint4*)&sm[nv + krow1 * AP + kd4] =
                make_uint4(f2tf32(pv1.x), f2tf32(pv1.y), f2tf32(pv1.z), f2tf32(pv1.w));
        }
        __syncthreads();
    }

    // ---- epilogue: normalize, store to [4096,1024] ----
    const float i0 = 1.f / l0r, i1 = 1.f / l1r;
#pragma unroll
    for (int nt = 0; nt < 8; nt++) {
        const int col = h * HDIM + nt * 8 + 2 * cq;
        float2 v0, v1;
        v0.x = o_[nt][0] * i0; v0.y = o_[nt][1] * i0;
        v1.x = o_[nt][2] * i1; v1.y = o_[nt][3] * i1;
        *(float2*)&out[(size_t)(b * NSEQ + q0 + wrow + r) * C_DIM + col]     = v0;
        *(float2*)&out[(size_t)(b * NSEQ + q0 + wrow + r + 8) * C_DIM + col] = v1;
    }
}

// ---------------------------------------------------------------------------
extern "C" void kernel_launch(void* const* d_in, const int* in_sizes, int n_in,
                              void* d_out, int out_size)
{
    const float* x      = (const float*)d_in[0];
    const float* w_qkv  = (const float*)d_in[1];
    const float* b_qkv  = (const float*)d_in[2];
    const float* w_proj = (const float*)d_in[3];
    const float* b_proj = (const float*)d_in[4];
    float* out = (float*)d_out;

    float *qkv_s, *att_s;
    cudaGetSymbolAddress((void**)&qkv_s, g_qkv);
    cudaGetSymbolAddress((void**)&att_s, g_att);

    cudaFuncSetAttribute(gemm_mma_tf32, cudaFuncAttributeMaxDynamicSharedMemorySize, GEMM_SMEM);
    cudaFuncSetAttribute(attn_mma, cudaFuncAttributeMaxDynamicSharedMemorySize, ATTN_SMEM);

    // 1) QKV projection: [4096,1024] @ [3072,1024]^T + b -> [4096,3072]
    dim3 g1(3 * C_DIM / 128, ROWS / 128);
    gemm_mma_tf32<<<g1, 256, GEMM_SMEM>>>(x, w_qkv, b_qkv, qkv_s, ROWS, 3 * C_DIM, C_DIM);

    // 2) Fused attention -> [4096,1024]
    dim3 g2(NSEQ / AQ, BATCH * NHEADS);
    attn_mma<<<g2, 512, ATTN_SMEM>>>(qkv_s, att_s);

    // 3) Output projection: [4096,1024] @ [1024,1024]^T + b -> out
    dim3 g3(C_DIM / 128, ROWS / 128);
    gemm_mma_tf32<<<g3, 256, GEMM_SMEM>>>(att_s, w_proj, b_proj, out, ROWS, C_DIM, C_DIM);
}

// round 6
// speedup vs baseline: 1.1090x; 1.1090x over previous
#include <cuda_runtime.h>
#include <cstdint>

#define C_DIM   1024
#define NSEQ    2048
#define NHEADS  16
#define HDIM    64
#define BATCH   2
#define ROWS    (BATCH * NSEQ)       // 4096
#define ATT_SCALE 0.125f             // 1/sqrt(64)

// Scratch (no allocations allowed in kernel_launch)
__device__ float g_qkv[ROWS * 3 * C_DIM];   // [4096, 3072]
__device__ float g_att[ROWS * C_DIM];       // [4096, 1024]

// ===========================================================================
// tf32 helpers (arch-independent PTX)
// ===========================================================================
__device__ __forceinline__ uint32_t f2tf32(float x) {
    uint32_t r;
    asm("cvt.rna.tf32.f32 %0, %1;" : "=r"(r) : "f"(x));
    return r;
}

// D += A @ B  for one m16n8k8 tf32 tile.
// GEMM uses natural k-slot mapping; attention uses the k-perm mapping
// (slot (c,c+4) -> physical (2c,2c+1)) -- valid since mma sums over k and
// A/B agree on the permutation.
__device__ __forceinline__ void mma_tf32(float* d, const uint32_t* a, const uint32_t* b) {
    asm volatile(
        "mma.sync.aligned.m16n8k8.row.col.f32.tf32.tf32.f32 "
        "{%0,%1,%2,%3}, {%4,%5,%6,%7}, {%8,%9}, {%0,%1,%2,%3};"
        : "+f"(d[0]), "+f"(d[1]), "+f"(d[2]), "+f"(d[3])
        : "r"(a[0]), "r"(a[1]), "r"(a[2]), "r"(a[3]), "r"(b[0]), "r"(b[1]));
}

// ===========================================================================
// tf32 mma.sync NT GEMM (R4 version -- measured best):
// C[M,Nt] = A[M,K] @ W[Nt,K]^T + bias[Nt]
// 128x128 tile, BK=32, 256 threads (8 warps, 64x32 each), 2 CTAs/SM.
// Pitch 36 (== 4 mod 32): scalar frag LDS conflict-free.
// ===========================================================================
#define GP 36
#define GSTAGE_F (2 * 128 * GP)          // A + B per stage (floats)
#define GEMM_SMEM (2 * GSTAGE_F * 4)     // 73728 B

__global__ __launch_bounds__(256, 2)
void gemm_mma_tf32(const float* __restrict__ A, const float* __restrict__ W,
                   const float* __restrict__ bias, float* __restrict__ Cout,
                   int M, int Nt, int K)
{
    extern __shared__ float smf[];
    const int t      = threadIdx.x;
    const int lane   = t & 31;
    const int r      = lane >> 2;
    const int cq     = lane & 3;
    const int wid    = t >> 5;
    const int warp_m = wid & 1;     // 2 warps over M (64 rows each)
    const int warp_n = wid >> 1;    // 4 warps over N (32 cols each)
    const int m0 = blockIdx.y << 7;
    const int n0 = blockIdx.x << 7;

    float acc[4][4][4];
#pragma unroll
    for (int i = 0; i < 4; i++)
#pragma unroll
        for (int j = 0; j < 4; j++)
#pragma unroll
            for (int e = 0; e < 4; e++) acc[i][j][e] = 0.f;

    const int nch = K / 32;
    const int grow = t >> 3;              // 0..31 (×4 via p)
    const int gc4  = (t & 7) << 2;        // 0..28

    float4 ra[4], rw[4];

#define LOAD_GMEM(cidx)                                                        \
    {                                                                          \
        const float* Ap = A + (size_t)m0 * K + (cidx) * 32;                    \
        const float* Wp = W + (size_t)n0 * K + (cidx) * 32;                    \
        _Pragma("unroll")                                                      \
        for (int p = 0; p < 4; p++) {                                          \
            int row = grow + p * 32;                                           \
            ra[p] = *(const float4*)(Ap + (size_t)row * K + gc4);              \
            rw[p] = *(const float4*)(Wp + (size_t)row * K + gc4);              \
        }                                                                      \
    }

#define STORE_STAGE(s)                                                         \
    {                                                                          \
        float* As = smf + (s) * GSTAGE_F;                                      \
        float* Bs = As + 128 * GP;                                             \
        _Pragma("unroll")                                                      \
        for (int p = 0; p < 4; p++) {                                          \
            int row = grow + p * 32;                                           \
            uint4 ua = make_uint4(f2tf32(ra[p].x), f2tf32(ra[p].y),            \
                                  f2tf32(ra[p].z), f2tf32(ra[p].w));           \
            uint4 uw = make_uint4(f2tf32(rw[p].x), f2tf32(rw[p].y),            \
                                  f2tf32(rw[p].z), f2tf32(rw[p].w));           \
            *(uint4*)&As[row * GP + gc4] = ua;                                 \
            *(uint4*)&Bs[row * GP + gc4] = uw;                                 \
        }                                                                      \
    }

    LOAD_GMEM(0);
    STORE_STAGE(0);
    __syncthreads();

    for (int c = 0; c < nch; c++) {
        const int s = c & 1;
        if (c + 1 < nch) LOAD_GMEM(c + 1);

        const float* As = smf + s * GSTAGE_F;
        const float* Bs = As + 128 * GP;
#pragma unroll
        for (int ks = 0; ks < 4; ks++) {
            uint32_t afr[4][4], bfr[4][2];
#pragma unroll
            for (int mt = 0; mt < 4; mt++) {
                const float* Ab = As + (warp_m * 64 + mt * 16) * GP + ks * 8;
                afr[mt][0] = __float_as_uint(Ab[r * GP + cq]);
                afr[mt][1] = __float_as_uint(Ab[(r + 8) * GP + cq]);
                afr[mt][2] = __float_as_uint(Ab[r * GP + cq + 4]);
                afr[mt][3] = __float_as_uint(Ab[(r + 8) * GP + cq + 4]);
            }
#pragma unroll
            for (int nt = 0; nt < 4; nt++) {
                const float* Bb = Bs + (warp_n * 32 + nt * 8 + r) * GP + ks * 8;
                bfr[nt][0] = __float_as_uint(Bb[cq]);
                bfr[nt][1] = __float_as_uint(Bb[cq + 4]);
            }
#pragma unroll
            for (int mt = 0; mt < 4; mt++)
#pragma unroll
                for (int nt = 0; nt < 4; nt++)
                    mma_tf32(acc[mt][nt], afr[mt], bfr[nt]);
        }

        if (c + 1 < nch) STORE_STAGE(s ^ 1);   // opposite buffer: safe pre-sync
        __syncthreads();
    }

    // Epilogue: direct stores with bias
    const int c2 = cq << 1;
#pragma unroll
    for (int nt = 0; nt < 4; nt++) {
        const int gn = n0 + warp_n * 32 + nt * 8 + c2;
        const float b0 = bias[gn], b1 = bias[gn + 1];
#pragma unroll
        for (int mt = 0; mt < 4; mt++) {
            const int gm = m0 + warp_m * 64 + mt * 16 + r;
            float2 v0, v1;
            v0.x = acc[mt][nt][0] + b0; v0.y = acc[mt][nt][1] + b1;
            v1.x = acc[mt][nt][2] + b0; v1.y = acc[mt][nt][3] + b1;
            *(float2*)&Cout[(size_t)gm * Nt + gn]       = v0;
            *(float2*)&Cout[(size_t)(gm + 8) * Nt + gn] = v1;
        }
    }
#undef LOAD_GMEM
#undef STORE_STAGE
}

// ===========================================================================
// Flash attention with tf32 mma.sync + k-perm register reuse.
// AQ=128 queries/CTA, 256 threads = 8 warps x 16 rows. 2 CTAs/SM (110.6KB smem)
// so a co-resident CTA's MMA phase hides this CTA's softmax phase.
// k-perm: S-mma output registers at lane (r,cq) are exactly the PV A-fragment
// slots -- P never touches shared memory.
// smem (floats, pitch 72 == 8 mod 32):
//   Qs[128][72] | K0[64][72] | V0[64][72] | K1[64][72] | V1[64][72]
// ===========================================================================
#define AQ      128
#define AP      72
#define OFF_K0  (AQ * AP)                    // 9216
#define OFF_V0  (OFF_K0 + 64 * AP)           // 13824
#define OFF_K1  (OFF_V0 + 64 * AP)           // 18432
#define OFF_V1  (OFF_K1 + 64 * AP)           // 23040
#define ATTN_SMEM ((OFF_V1 + 64 * AP) * 4)   // 110592 B

__global__ __launch_bounds__(256, 2)
void attn_mma(const float* __restrict__ qkv, float* __restrict__ out)
{
    extern __shared__ float sm[];
    const int t    = threadIdx.x;
    const int lane = t & 31;
    const int wid  = t >> 5;
    const int r    = lane >> 2;
    const int cq   = lane & 3;
    const int q0   = blockIdx.x * AQ;
    const int b    = blockIdx.y >> 4;
    const int h    = blockIdx.y & 15;
    const int rs   = 3 * C_DIM;

    const float* qb = qkv + ((size_t)(b * NSEQ + q0) * 3) * C_DIM + h * HDIM;
    const float* kb = qkv + ((size_t)(b * NSEQ) * 3 + 1) * C_DIM + h * HDIM;
    const float* vb = qkv + ((size_t)(b * NSEQ) * 3 + 2) * C_DIM + h * HDIM;

    // ---- stage Q (tf32): 128 rows x 16 float4 = 2048 slots ----
#pragma unroll
    for (int p = 0; p < 8; p++) {
        int fi  = t + 256 * p;
        int row = fi >> 4;
        int d4  = (fi & 15) << 2;
        float4 v = *(const float4*)(qb + (size_t)row * rs + d4);
        uint4 u = make_uint4(f2tf32(v.x), f2tf32(v.y), f2tf32(v.z), f2tf32(v.w));
        *(uint4*)&sm[row * AP + d4] = u;
    }

    // ---- stage K/V tile 0: 64 rows x 16 float4 = 1024 slots each ----
#pragma unroll
    for (int p = 0; p < 4; p++) {
        int fi  = t + 256 * p;
        int row = fi >> 4;
        int d4  = (fi & 15) << 2;
        float4 kv = *(const float4*)(kb + (size_t)row * rs + d4);
        float4 vv = *(const float4*)(vb + (size_t)row * rs + d4);
        *(uint4*)&sm[OFF_K0 + row * AP + d4] =
            make_uint4(f2tf32(kv.x), f2tf32(kv.y), f2tf32(kv.z), f2tf32(kv.w));
        *(uint4*)&sm[OFF_V0 + row * AP + d4] =
            make_uint4(f2tf32(vv.x), f2tf32(vv.y), f2tf32(vv.z), f2tf32(vv.w));
    }
    __syncthreads();

    float o_[8][4];
#pragma unroll
    for (int nt = 0; nt < 8; nt++)
#pragma unroll
        for (int e = 0; e < 4; e++) o_[nt][e] = 0.f;
    float m0r = -1e30f, m1r = -1e30f, l0r = 0.f, l1r = 0.f;

    const int wrow = wid * 16;   // warp's query-row base within block

    for (int kt = 0; kt < NSEQ / 64; kt++) {
        const int s = kt & 1;
        const int koff = s ? OFF_K1 : OFF_K0;
        const int voff = s ? OFF_V1 : OFF_V0;

        // ---- S = Q @ K^T (warp: 16 rows x 64 cols) ----
        float s_[8][4];
#pragma unroll
        for (int nt = 0; nt < 8; nt++)
#pragma unroll
            for (int e = 0; e < 4; e++) s_[nt][e] = 0.f;

#pragma unroll
        for (int ks = 0; ks < 8; ks++) {
            uint32_t a[4];
            const float* Qb = &sm[wrow * AP + ks * 8 + 2 * cq];
            float2 qlo = *(const float2*)&Qb[r * AP];
            float2 qhi = *(const float2*)&Qb[(r + 8) * AP];
            a[0] = __float_as_uint(qlo.x);
            a[1] = __float_as_uint(qhi.x);
            a[2] = __float_as_uint(qlo.y);
            a[3] = __float_as_uint(qhi.y);
#pragma unroll
            for (int nt = 0; nt < 8; nt++) {
                float2 kv = *(const float2*)&sm[koff + (nt * 8 + r) * AP + ks * 8 + 2 * cq];
                uint32_t bf[2];
                bf[0] = __float_as_uint(kv.x);
                bf[1] = __float_as_uint(kv.y);
                mma_tf32(s_[nt], a, bf);
            }
        }

        // ---- prefetch next K/V tile (hidden behind softmax + PV) ----
        float4 pk[4], pv[4];
        if (kt + 1 < NSEQ / 64) {
            const float* kn = kb + (size_t)((kt + 1) * 64) * rs;
            const float* vn = vb + (size_t)((kt + 1) * 64) * rs;
#pragma unroll
            for (int p = 0; p < 4; p++) {
                int fi  = t + 256 * p;
                int row = fi >> 4;
                int d4  = (fi & 15) << 2;
                pk[p] = *(const float4*)(kn + (size_t)row * rs + d4);
                pv[p] = *(const float4*)(vn + (size_t)row * rs + d4);
            }
        }

        // ---- online softmax (rows r and r+8; reduce over c-quad) ----
        float ml0 = -1e30f, ml1 = -1e30f;
#pragma unroll
        for (int nt = 0; nt < 8; nt++) {
            s_[nt][0] *= ATT_SCALE; s_[nt][1] *= ATT_SCALE;
            s_[nt][2] *= ATT_SCALE; s_[nt][3] *= ATT_SCALE;
            ml0 = fmaxf(ml0, fmaxf(s_[nt][0], s_[nt][1]));
            ml1 = fmaxf(ml1, fmaxf(s_[nt][2], s_[nt][3]));
        }
        ml0 = fmaxf(ml0, __shfl_xor_sync(0xffffffffu, ml0, 1));
        ml0 = fmaxf(ml0, __shfl_xor_sync(0xffffffffu, ml0, 2));
        ml1 = fmaxf(ml1, __shfl_xor_sync(0xffffffffu, ml1, 1));
        ml1 = fmaxf(ml1, __shfl_xor_sync(0xffffffffu, ml1, 2));

        float mn0 = fmaxf(m0r, ml0), mn1 = fmaxf(m1r, ml1);
        float cr0 = __expf(m0r - mn0), cr1 = __expf(m1r - mn1);
        m0r = mn0; m1r = mn1;

        float rs0 = 0.f, rs1 = 0.f;
#pragma unroll
        for (int nt = 0; nt < 8; nt++) {
            s_[nt][0] = __expf(s_[nt][0] - mn0);
            s_[nt][1] = __expf(s_[nt][1] - mn0);
            s_[nt][2] = __expf(s_[nt][2] - mn1);
            s_[nt][3] = __expf(s_[nt][3] - mn1);
            rs0 += s_[nt][0] + s_[nt][1];
            rs1 += s_[nt][2] + s_[nt][3];
        }
        rs0 += __shfl_xor_sync(0xffffffffu, rs0, 1);
        rs0 += __shfl_xor_sync(0xffffffffu, rs0, 2);
        rs1 += __shfl_xor_sync(0xffffffffu, rs1, 1);
        rs1 += __shfl_xor_sync(0xffffffffu, rs1, 2);
        l0r = l0r * cr0 + rs0;
        l1r = l1r * cr1 + rs1;

#pragma unroll
        for (int nt = 0; nt < 8; nt++) {
            o_[nt][0] *= cr0; o_[nt][1] *= cr0;
            o_[nt][2] *= cr1; o_[nt][3] *= cr1;
        }

        // ---- O += P @ V : P straight from s_ registers (k-perm) ----
        //   a0 = P[r][ks*8+2cq]   = s_[ks][0]
        //   a1 = P[r+8][ks*8+2cq] = s_[ks][2]
        //   a2 = P[r][ks*8+2cq+1] = s_[ks][1]
        //   a3 = P[r+8][ks*8+2cq+1] = s_[ks][3]
        // V b-frags: physical key rows ks*8+2cq, +1 at col nt*8+r.
#pragma unroll
        for (int ks = 0; ks < 8; ks++) {
            uint32_t a[4];
            a[0] = f2tf32(s_[ks][0]);
            a[1] = f2tf32(s_[ks][2]);
            a[2] = f2tf32(s_[ks][1]);
            a[3] = f2tf32(s_[ks][3]);
            const float* Vb = &sm[voff + (ks * 8 + 2 * cq) * AP + r];
#pragma unroll
            for (int nt = 0; nt < 8; nt++) {
                uint32_t bf[2];
                bf[0] = __float_as_uint(Vb[nt * 8]);
                bf[1] = __float_as_uint(Vb[nt * 8 + AP]);
                mma_tf32(o_[nt], a, bf);
            }
        }

        // ---- stage next tile into opposite buffer, then one barrier ----
        if (kt + 1 < NSEQ / 64) {
            const int nk = s ? OFF_K0 : OFF_K1;
            const int nv = s ? OFF_V0 : OFF_V1;
#pragma unroll
            for (int p = 0; p < 4; p++) {
                int fi  = t + 256 * p;
                int row = fi >> 4;
                int d4  = (fi & 15) << 2;
                *(uint4*)&sm[nk + row * AP + d4] =
                    make_uint4(f2tf32(pk[p].x), f2tf32(pk[p].y),
                               f2tf32(pk[p].z), f2tf32(pk[p].w));
                *(uint4*)&sm[nv + row * AP + d4] =
                    make_uint4(f2tf32(pv[p].x), f2tf32(pv[p].y),
                               f2tf32(pv[p].z), f2tf32(pv[p].w));
            }
        }
        __syncthreads();
    }

    // ---- epilogue: normalize, store to [4096,1024] ----
    const float i0 = 1.f / l0r, i1 = 1.f / l1r;
#pragma unroll
    for (int nt = 0; nt < 8; nt++) {
        const int col = h * HDIM + nt * 8 + 2 * cq;
        float2 v0, v1;
        v0.x = o_[nt][0] * i0; v0.y = o_[nt][1] * i0;
        v1.x = o_[nt][2] * i1; v1.y = o_[nt][3] * i1;
        *(float2*)&out[(size_t)(b * NSEQ + q0 + wrow + r) * C_DIM + col]     = v0;
        *(float2*)&out[(size_t)(b * NSEQ + q0 + wrow + r + 8) * C_DIM + col] = v1;
    }
}

// ---------------------------------------------------------------------------
extern "C" void kernel_launch(void* const* d_in, const int* in_sizes, int n_in,
                              void* d_out, int out_size)
{
    const float* x      = (const float*)d_in[0];
    const float* w_qkv  = (const float*)d_in[1];
    const float* b_qkv  = (const float*)d_in[2];
    const float* w_proj = (const float*)d_in[3];
    const float* b_proj = (const float*)d_in[4];
    float* out = (float*)d_out;

    float *qkv_s, *att_s;
    cudaGetSymbolAddress((void**)&qkv_s, g_qkv);
    cudaGetSymbolAddress((void**)&att_s, g_att);

    cudaFuncSetAttribute(gemm_mma_tf32, cudaFuncAttributeMaxDynamicSharedMemorySize, GEMM_SMEM);
    cudaFuncSetAttribute(attn_mma, cudaFuncAttributeMaxDynamicSharedMemorySize, ATTN_SMEM);

    // 1) QKV projection: [4096,1024] @ [3072,1024]^T + b -> [4096,3072]
    dim3 g1(3 * C_DIM / 128, ROWS / 128);
    gemm_mma_tf32<<<g1, 256, GEMM_SMEM>>>(x, w_qkv, b_qkv, qkv_s, ROWS, 3 * C_DIM, C_DIM);

    // 2) Fused attention -> [4096,1024]
    dim3 g2(NSEQ / AQ, BATCH * NHEADS);
    attn_mma<<<g2, 256, ATTN_SMEM>>>(qkv_s, att_s);

    // 3) Output projection: [4096,1024] @ [1024,1024]^T + b -> out
    dim3 g3(C_DIM / 128, ROWS / 128);
    gemm_mma_tf32<<<g3, 256, GEMM_SMEM>>>(att_s, w_proj, b_proj, out, ROWS, C_DIM, C_DIM);
}

// round 7
// speedup vs baseline: 1.1940x; 1.0766x over previous
#include <cuda_runtime.h>
#include <cstdint>

#define C_DIM   1024
#define NSEQ    2048
#define NHEADS  16
#define HDIM    64
#define BATCH   2
#define ROWS    (BATCH * NSEQ)       // 4096
#define ATT_SCALE 0.125f             // 1/sqrt(64)

// Scratch (no allocations allowed in kernel_launch)
__device__ float g_qkv[ROWS * 3 * C_DIM];       // [4096, 3072] (tf32-rounded)
__device__ float g_att[ROWS * C_DIM];           // [4096, 1024] (tf32-rounded)
__device__ float g_xtf[ROWS * C_DIM];           // x, tf32-rounded
__device__ float g_wqkv_tf[3 * C_DIM * C_DIM];  // w_qkv, tf32-rounded
__device__ float g_wproj_tf[C_DIM * C_DIM];     // w_proj, tf32-rounded

// ===========================================================================
// tf32 helpers (arch-independent PTX)
// ===========================================================================
__device__ __forceinline__ uint32_t f2tf32(float x) {
    uint32_t r;
    asm("cvt.rna.tf32.f32 %0, %1;" : "=r"(r) : "f"(x));
    return r;
}

__device__ __forceinline__ void mma_tf32(float* d, const uint32_t* a, const uint32_t* b) {
    asm volatile(
        "mma.sync.aligned.m16n8k8.row.col.f32.tf32.tf32.f32 "
        "{%0,%1,%2,%3}, {%4,%5,%6,%7}, {%8,%9}, {%0,%1,%2,%3};"
        : "+f"(d[0]), "+f"(d[1]), "+f"(d[2]), "+f"(d[3])
        : "r"(a[0]), "r"(a[1]), "r"(a[2]), "r"(a[3]), "r"(b[0]), "r"(b[1]));
}

// ===========================================================================
// Pre-pass: round fp32 -> tf32-in-fp32 (rna). Grid-stride over float4.
// ===========================================================================
__global__ void cvt_tf32_pass(const float* __restrict__ in, float* __restrict__ outp, int n4)
{
    int i = blockIdx.x * blockDim.x + threadIdx.x;
    int stride = gridDim.x * blockDim.x;
    for (; i < n4; i += stride) {
        float4 v = ((const float4*)in)[i];
        uint4 u = make_uint4(f2tf32(v.x), f2tf32(v.y), f2tf32(v.z), f2tf32(v.w));
        ((uint4*)outp)[i] = u;
    }
}

// ===========================================================================
// tf32 mma.sync NT GEMM (R4 layout -- measured best):
// C[M,Nt] = A[M,K] @ W[Nt,K]^T + bias[Nt]
// Inputs are PRE-ROUNDED to tf32 -> staging is a pure copy (no cvt).
// 128x128 tile, BK=32, 256 threads (8 warps, 64x32 each), 2 CTAs/SM.
// Pitch 36 (== 4 mod 32): scalar frag LDS conflict-free.
// round_out != 0: epilogue emits tf32-rounded values (for downstream mma).
// ===========================================================================
#define GP 36
#define GSTAGE_F (2 * 128 * GP)          // A + B per stage (floats)
#define GEMM_SMEM (2 * GSTAGE_F * 4)     // 73728 B

__global__ __launch_bounds__(256, 2)
void gemm_mma_tf32(const float* __restrict__ A, const float* __restrict__ W,
                   const float* __restrict__ bias, float* __restrict__ Cout,
                   int M, int Nt, int K, int round_out)
{
    extern __shared__ float smf[];
    const int t      = threadIdx.x;
    const int lane   = t & 31;
    const int r      = lane >> 2;
    const int cq     = lane & 3;
    const int wid    = t >> 5;
    const int warp_m = wid & 1;     // 2 warps over M (64 rows each)
    const int warp_n = wid >> 1;    // 4 warps over N (32 cols each)
    const int m0 = blockIdx.y << 7;
    const int n0 = blockIdx.x << 7;

    float acc[4][4][4];
#pragma unroll
    for (int i = 0; i < 4; i++)
#pragma unroll
        for (int j = 0; j < 4; j++)
#pragma unroll
            for (int e = 0; e < 4; e++) acc[i][j][e] = 0.f;

    const int nch = K / 32;
    const int grow = t >> 3;              // 0..31 (×4 via p)
    const int gc4  = (t & 7) << 2;        // 0..28

    float4 ra[4], rw[4];

#define LOAD_GMEM(cidx)                                                        \
    {                                                                          \
        const float* Ap = A + (size_t)m0 * K + (cidx) * 32;                    \
        const float* Wp = W + (size_t)n0 * K + (cidx) * 32;                    \
        _Pragma("unroll")                                                      \
        for (int p = 0; p < 4; p++) {                                          \
            int row = grow + p * 32;                                           \
            ra[p] = *(const float4*)(Ap + (size_t)row * K + gc4);              \
            rw[p] = *(const float4*)(Wp + (size_t)row * K + gc4);              \
        }                                                                      \
    }

#define STORE_STAGE(s)                                                         \
    {                                                                          \
        float* As = smf + (s) * GSTAGE_F;                                      \
        float* Bs = As + 128 * GP;                                             \
        _Pragma("unroll")                                                      \
        for (int p = 0; p < 4; p++) {                                          \
            int row = grow + p * 32;                                           \
            *(float4*)&As[row * GP + gc4] = ra[p];                             \
            *(float4*)&Bs[row * GP + gc4] = rw[p];                             \
        }                                                                      \
    }

    LOAD_GMEM(0);
    STORE_STAGE(0);
    __syncthreads();

    for (int c = 0; c < nch; c++) {
        const int s = c & 1;
        if (c + 1 < nch) LOAD_GMEM(c + 1);

        const float* As = smf + s * GSTAGE_F;
        const float* Bs = As + 128 * GP;
#pragma unroll
        for (int ks = 0; ks < 4; ks++) {
            uint32_t afr[4][4], bfr[4][2];
#pragma unroll
            for (int mt = 0; mt < 4; mt++) {
                const float* Ab = As + (warp_m * 64 + mt * 16) * GP + ks * 8;
                afr[mt][0] = __float_as_uint(Ab[r * GP + cq]);
                afr[mt][1] = __float_as_uint(Ab[(r + 8) * GP + cq]);
                afr[mt][2] = __float_as_uint(Ab[r * GP + cq + 4]);
                afr[mt][3] = __float_as_uint(Ab[(r + 8) * GP + cq + 4]);
            }
#pragma unroll
            for (int nt = 0; nt < 4; nt++) {
                const float* Bb = Bs + (warp_n * 32 + nt * 8 + r) * GP + ks * 8;
                bfr[nt][0] = __float_as_uint(Bb[cq]);
                bfr[nt][1] = __float_as_uint(Bb[cq + 4]);
            }
#pragma unroll
            for (int mt = 0; mt < 4; mt++)
#pragma unroll
                for (int nt = 0; nt < 4; nt++)
                    mma_tf32(acc[mt][nt], afr[mt], bfr[nt]);
        }

        if (c + 1 < nch) STORE_STAGE(s ^ 1);   // opposite buffer: safe pre-sync
        __syncthreads();
    }

    // Epilogue: bias, optional tf32 rounding, direct stores
    const int c2 = cq << 1;
#pragma unroll
    for (int nt = 0; nt < 4; nt++) {
        const int gn = n0 + warp_n * 32 + nt * 8 + c2;
        const float b0 = bias[gn], b1 = bias[gn + 1];
#pragma unroll
        for (int mt = 0; mt < 4; mt++) {
            const int gm = m0 + warp_m * 64 + mt * 16 + r;
            float2 v0, v1;
            v0.x = acc[mt][nt][0] + b0; v0.y = acc[mt][nt][1] + b1;
            v1.x = acc[mt][nt][2] + b0; v1.y = acc[mt][nt][3] + b1;
            if (round_out) {
                v0.x = __uint_as_float(f2tf32(v0.x));
                v0.y = __uint_as_float(f2tf32(v0.y));
                v1.x = __uint_as_float(f2tf32(v1.x));
                v1.y = __uint_as_float(f2tf32(v1.y));
            }
            *(float2*)&Cout[(size_t)gm * Nt + gn]       = v0;
            *(float2*)&Cout[(size_t)(gm + 8) * Nt + gn] = v1;
        }
    }
#undef LOAD_GMEM
#undef STORE_STAGE
}

// ===========================================================================
// Flash attention with tf32 mma.sync + k-perm register reuse (R5 shape --
// measured best). AQ=256, 512 threads = 16 warps x 16 rows. Inputs are
// PRE-ROUNDED tf32 (QKV gemm epilogue) -> staging is pure copy.
// Output written tf32-rounded (feeds proj gemm).
// smem (floats, pitch 72): Qs[256][72] | K0 | V0 | K1 | V1 (64 rows each)
// ===========================================================================
#define AQ      256
#define AP      72
#define OFF_K0  (AQ * AP)
#define OFF_V0  (OFF_K0 + 64 * AP)
#define OFF_K1  (OFF_V0 + 64 * AP)
#define OFF_V1  (OFF_K1 + 64 * AP)
#define ATTN_SMEM ((OFF_V1 + 64 * AP) * 4)   // 147456 B

__global__ __launch_bounds__(512)
void attn_mma(const float* __restrict__ qkv, float* __restrict__ out)
{
    extern __shared__ float sm[];
    const int t    = threadIdx.x;
    const int lane = t & 31;
    const int wid  = t >> 5;
    const int r    = lane >> 2;
    const int cq   = lane & 3;
    const int q0   = blockIdx.x * AQ;
    const int b    = blockIdx.y >> 4;
    const int h    = blockIdx.y & 15;
    const int rs   = 3 * C_DIM;

    const float* qb = qkv + ((size_t)(b * NSEQ + q0) * 3) * C_DIM + h * HDIM;
    const float* kb = qkv + ((size_t)(b * NSEQ) * 3 + 1) * C_DIM + h * HDIM;
    const float* vb = qkv + ((size_t)(b * NSEQ) * 3 + 2) * C_DIM + h * HDIM;

    // ---- stage Q (pure copy; already tf32-rounded) ----
#pragma unroll
    for (int p = 0; p < 8; p++) {
        int fi  = t + 512 * p;
        int row = fi >> 4;
        int d4  = (fi & 15) << 2;
        *(float4*)&sm[row * AP + d4] = *(const float4*)(qb + (size_t)row * rs + d4);
    }

    const int krow0 = t >> 4;              // 0..31
    const int krow1 = krow0 + 32;
    const int kd4   = (t & 15) << 2;

    // ---- stage K/V tile 0 ----
    *(float4*)&sm[OFF_K0 + krow0 * AP + kd4] = *(const float4*)(kb + (size_t)krow0 * rs + kd4);
    *(float4*)&sm[OFF_K0 + krow1 * AP + kd4] = *(const float4*)(kb + (size_t)krow1 * rs + kd4);
    *(float4*)&sm[OFF_V0 + krow0 * AP + kd4] = *(const float4*)(vb + (size_t)krow0 * rs + kd4);
    *(float4*)&sm[OFF_V0 + krow1 * AP + kd4] = *(const float4*)(vb + (size_t)krow1 * rs + kd4);
    __syncthreads();

    float o_[8][4];
#pragma unroll
    for (int nt = 0; nt < 8; nt++)
#pragma unroll
        for (int e = 0; e < 4; e++) o_[nt][e] = 0.f;
    float m0r = -1e30f, m1r = -1e30f, l0r = 0.f, l1r = 0.f;

    const int wrow = wid * 16;   // warp's query-row base within block

    for (int kt = 0; kt < NSEQ / 64; kt++) {
        const int s = kt & 1;
        const int koff = s ? OFF_K1 : OFF_K0;
        const int voff = s ? OFF_V1 : OFF_V0;

        // ---- S = Q @ K^T (warp: 16 rows x 64 cols), LDS.64 frags ----
        float s_[8][4];
#pragma unroll
        for (int nt = 0; nt < 8; nt++)
#pragma unroll
            for (int e = 0; e < 4; e++) s_[nt][e] = 0.f;

#pragma unroll
        for (int ks = 0; ks < 8; ks++) {
            uint32_t a[4];
            const float* Qb = &sm[wrow * AP + ks * 8 + 2 * cq];
            float2 qlo = *(const float2*)&Qb[r * AP];
            float2 qhi = *(const float2*)&Qb[(r + 8) * AP];
            a[0] = __float_as_uint(qlo.x);
            a[1] = __float_as_uint(qhi.x);
            a[2] = __float_as_uint(qlo.y);
            a[3] = __float_as_uint(qhi.y);
#pragma unroll
            for (int nt = 0; nt < 8; nt++) {
                float2 kv = *(const float2*)&sm[koff + (nt * 8 + r) * AP + ks * 8 + 2 * cq];
                uint32_t bf[2];
                bf[0] = __float_as_uint(kv.x);
                bf[1] = __float_as_uint(kv.y);
                mma_tf32(s_[nt], a, bf);
            }
        }

        // ---- prefetch next K/V tile ----
        float4 pk0, pk1, pv0, pv1;
        if (kt + 1 < NSEQ / 64) {
            const float* kn = kb + (size_t)((kt + 1) * 64) * rs;
            const float* vn = vb + (size_t)((kt + 1) * 64) * rs;
            pk0 = *(const float4*)(kn + (size_t)krow0 * rs + kd4);
            pk1 = *(const float4*)(kn + (size_t)krow1 * rs + kd4);
            pv0 = *(const float4*)(vn + (size_t)krow0 * rs + kd4);
            pv1 = *(const float4*)(vn + (size_t)krow1 * rs + kd4);
        }

        // ---- online softmax ----
        float ml0 = -1e30f, ml1 = -1e30f;
#pragma unroll
        for (int nt = 0; nt < 8; nt++) {
            s_[nt][0] *= ATT_SCALE; s_[nt][1] *= ATT_SCALE;
            s_[nt][2] *= ATT_SCALE; s_[nt][3] *= ATT_SCALE;
            ml0 = fmaxf(ml0, fmaxf(s_[nt][0], s_[nt][1]));
            ml1 = fmaxf(ml1, fmaxf(s_[nt][2], s_[nt][3]));
        }
        ml0 = fmaxf(ml0, __shfl_xor_sync(0xffffffffu, ml0, 1));
        ml0 = fmaxf(ml0, __shfl_xor_sync(0xffffffffu, ml0, 2));
        ml1 = fmaxf(ml1, __shfl_xor_sync(0xffffffffu, ml1, 1));
        ml1 = fmaxf(ml1, __shfl_xor_sync(0xffffffffu, ml1, 2));

        float mn0 = fmaxf(m0r, ml0), mn1 = fmaxf(m1r, ml1);
        float cr0 = __expf(m0r - mn0), cr1 = __expf(m1r - mn1);
        m0r = mn0; m1r = mn1;

        float rs0 = 0.f, rs1 = 0.f;
#pragma unroll
        for (int nt = 0; nt < 8; nt++) {
            s_[nt][0] = __expf(s_[nt][0] - mn0);
            s_[nt][1] = __expf(s_[nt][1] - mn0);
            s_[nt][2] = __expf(s_[nt][2] - mn1);
            s_[nt][3] = __expf(s_[nt][3] - mn1);
            rs0 += s_[nt][0] + s_[nt][1];
            rs1 += s_[nt][2] + s_[nt][3];
        }
        rs0 += __shfl_xor_sync(0xffffffffu, rs0, 1);
        rs0 += __shfl_xor_sync(0xffffffffu, rs0, 2);
        rs1 += __shfl_xor_sync(0xffffffffu, rs1, 1);
        rs1 += __shfl_xor_sync(0xffffffffu, rs1, 2);
        l0r = l0r * cr0 + rs0;
        l1r = l1r * cr1 + rs1;

#pragma unroll
        for (int nt = 0; nt < 8; nt++) {
            o_[nt][0] *= cr0; o_[nt][1] *= cr0;
            o_[nt][2] *= cr1; o_[nt][3] *= cr1;
        }

        // ---- O += P @ V : P straight from s_ registers (k-perm) ----
#pragma unroll
        for (int ks = 0; ks < 8; ks++) {
            uint32_t a[4];
            a[0] = f2tf32(s_[ks][0]);
            a[1] = f2tf32(s_[ks][2]);
            a[2] = f2tf32(s_[ks][1]);
            a[3] = f2tf32(s_[ks][3]);
            const float* Vb = &sm[voff + (ks * 8 + 2 * cq) * AP + r];
#pragma unroll
            for (int nt = 0; nt < 8; nt++) {
                uint32_t bf[2];
                bf[0] = __float_as_uint(Vb[nt * 8]);
                bf[1] = __float_as_uint(Vb[nt * 8 + AP]);
                mma_tf32(o_[nt], a, bf);
            }
        }

        // ---- stage next tile into opposite buffer, then one barrier ----
        if (kt + 1 < NSEQ / 64) {
            const int nk = s ? OFF_K0 : OFF_K1;
            const int nv = s ? OFF_V0 : OFF_V1;
            *(float4*)&sm[nk + krow0 * AP + kd4] = pk0;
            *(float4*)&sm[nk + krow1 * AP + kd4] = pk1;
            *(float4*)&sm[nv + krow0 * AP + kd4] = pv0;
            *(float4*)&sm[nv + krow1 * AP + kd4] = pv1;
        }
        __syncthreads();
    }

    // ---- epilogue: normalize, round to tf32 (feeds proj gemm), store ----
    const float i0 = 1.f / l0r, i1 = 1.f / l1r;
#pragma unroll
    for (int nt = 0; nt < 8; nt++) {
        const int col = h * HDIM + nt * 8 + 2 * cq;
        float2 v0, v1;
        v0.x = __uint_as_float(f2tf32(o_[nt][0] * i0));
        v0.y = __uint_as_float(f2tf32(o_[nt][1] * i0));
        v1.x = __uint_as_float(f2tf32(o_[nt][2] * i1));
        v1.y = __uint_as_float(f2tf32(o_[nt][3] * i1));
        *(float2*)&out[(size_t)(b * NSEQ + q0 + wrow + r) * C_DIM + col]     = v0;
        *(float2*)&out[(size_t)(b * NSEQ + q0 + wrow + r + 8) * C_DIM + col] = v1;
    }
}

// ---------------------------------------------------------------------------
extern "C" void kernel_launch(void* const* d_in, const int* in_sizes, int n_in,
                              void* d_out, int out_size)
{
    const float* x      = (const float*)d_in[0];
    const float* w_qkv  = (const float*)d_in[1];
    const float* b_qkv  = (const float*)d_in[2];
    const float* w_proj = (const float*)d_in[3];
    const float* b_proj = (const float*)d_in[4];
    float* out = (float*)d_out;

    float *qkv_s, *att_s, *xtf, *wqtf, *wptf;
    cudaGetSymbolAddress((void**)&qkv_s, g_qkv);
    cudaGetSymbolAddress((void**)&att_s, g_att);
    cudaGetSymbolAddress((void**)&xtf,   g_xtf);
    cudaGetSymbolAddress((void**)&wqtf,  g_wqkv_tf);
    cudaGetSymbolAddress((void**)&wptf,  g_wproj_tf);

    cudaFuncSetAttribute(gemm_mma_tf32, cudaFuncAttributeMaxDynamicSharedMemorySize, GEMM_SMEM);
    cudaFuncSetAttribute(attn_mma, cudaFuncAttributeMaxDynamicSharedMemorySize, ATTN_SMEM);

    // 0) Pre-round inputs to tf32 (hoists all cvt out of GEMM/attention loops)
    cvt_tf32_pass<<<592, 256>>>(x,      xtf,  ROWS * C_DIM / 4);
    cvt_tf32_pass<<<592, 256>>>(w_qkv,  wqtf, 3 * C_DIM * C_DIM / 4);
    cvt_tf32_pass<<<592, 256>>>(w_proj, wptf, C_DIM * C_DIM / 4);

    // 1) QKV projection -> tf32-rounded [4096,3072]
    dim3 g1(3 * C_DIM / 128, ROWS / 128);
    gemm_mma_tf32<<<g1, 256, GEMM_SMEM>>>(xtf, wqtf, b_qkv, qkv_s,
                                          ROWS, 3 * C_DIM, C_DIM, 1);

    // 2) Fused attention -> tf32-rounded [4096,1024]
    dim3 g2(NSEQ / AQ, BATCH * NHEADS);
    attn_mma<<<g2, 512, ATTN_SMEM>>>(qkv_s, att_s);

    // 3) Output projection -> fp32 out
    dim3 g3(C_DIM / 128, ROWS / 128);
    gemm_mma_tf32<<<g3, 256, GEMM_SMEM>>>(att_s, wptf, b_proj, out,
                                          ROWS, C_DIM, C_DIM, 0);
}

// round 8
// speedup vs baseline: 1.2852x; 1.0764x over previous
#include <cuda_runtime.h>
#include <cstdint>

#define C_DIM   1024
#define NSEQ    2048
#define NHEADS  16
#define HDIM    64
#define BATCH   2
#define ROWS    (BATCH * NSEQ)       // 4096
#define ATT_SCALE 0.125f             // 1/sqrt(64)

// Scratch (no allocations allowed in kernel_launch)
__device__ float g_qkv[ROWS * 3 * C_DIM];       // [4096, 3072] (tf32-rounded)
__device__ float g_att[ROWS * C_DIM];           // [4096, 1024] (tf32-rounded)
__device__ float g_xtf[ROWS * C_DIM];           // x, tf32-rounded
__device__ float g_wqkv_tf[3 * C_DIM * C_DIM];  // w_qkv, tf32-rounded
__device__ float g_wproj_tf[C_DIM * C_DIM];     // w_proj, tf32-rounded

// ===========================================================================
// helpers (arch-independent PTX)
// ===========================================================================
__device__ __forceinline__ uint32_t f2tf32(float x) {
    uint32_t r;
    asm("cvt.rna.tf32.f32 %0, %1;" : "=r"(r) : "f"(x));
    return r;
}
__device__ __forceinline__ uint32_t smem_u32(const void* p) {
    uint32_t a;
    asm("{ .reg .u64 t; cvta.to.shared.u64 t, %1; cvt.u32.u64 %0, t; }"
        : "=r"(a) : "l"(p));
    return a;
}
// ldmatrix x4 on fp32 data viewed as b16 pairs: each 8x8-b16 matrix is an
// 8x4-fp32 tile; lane i receives fp32 element (row i/4, col i%4).
__device__ __forceinline__ void ldsm_x4(uint32_t addr, uint32_t* d) {
    asm volatile("ldmatrix.sync.aligned.m8n8.x4.shared.b16 {%0,%1,%2,%3}, [%4];"
                 : "=r"(d[0]), "=r"(d[1]), "=r"(d[2]), "=r"(d[3]) : "r"(addr));
}

__device__ __forceinline__ void mma_tf32(float* d, const uint32_t* a, const uint32_t* b) {
    asm volatile(
        "mma.sync.aligned.m16n8k8.row.col.f32.tf32.tf32.f32 "
        "{%0,%1,%2,%3}, {%4,%5,%6,%7}, {%8,%9}, {%0,%1,%2,%3};"
        : "+f"(d[0]), "+f"(d[1]), "+f"(d[2]), "+f"(d[3])
        : "r"(a[0]), "r"(a[1]), "r"(a[2]), "r"(a[3]), "r"(b[0]), "r"(b[1]));
}

// ===========================================================================
// Pre-pass: round fp32 -> tf32-in-fp32 (rna). Grid-stride over float4.
// ===========================================================================
__global__ void cvt_tf32_pass(const float* __restrict__ in, float* __restrict__ outp, int n4)
{
    int i = blockIdx.x * blockDim.x + threadIdx.x;
    int stride = gridDim.x * blockDim.x;
    for (; i < n4; i += stride) {
        float4 v = ((const float4*)in)[i];
        uint4 u = make_uint4(f2tf32(v.x), f2tf32(v.y), f2tf32(v.z), f2tf32(v.w));
        ((uint4*)outp)[i] = u;
    }
}

// ===========================================================================
// tf32 mma.sync NT GEMM with ldmatrix fragment loads:
// C[M,Nt] = A[M,K] @ W[Nt,K]^T + bias[Nt]
// Inputs PRE-ROUNDED tf32. 128x128 tile, BK=32, 256 threads, 2 CTAs/SM.
// Pitch 36 floats (144B; 144 mod 128 = 16 -> the 8 row-addresses of each
// ldmatrix matrix hit distinct 16B bank groups: conflict-free).
// ===========================================================================
#define GP 36
#define GSTAGE_F (2 * 128 * GP)          // A + B per stage (floats)
#define GEMM_SMEM (2 * GSTAGE_F * 4)     // 73728 B

__global__ __launch_bounds__(256, 2)
void gemm_mma_tf32(const float* __restrict__ A, const float* __restrict__ W,
                   const float* __restrict__ bias, float* __restrict__ Cout,
                   int M, int Nt, int K, int round_out)
{
    extern __shared__ float smf[];
    const uint32_t smb = smem_u32(smf);
    const int t      = threadIdx.x;
    const int lane   = t & 31;
    const int r      = lane >> 2;
    const int cq     = lane & 3;
    const int g      = lane >> 3;        // ldmatrix address group 0..3
    const int j      = lane & 7;         // row within group
    const int wid    = t >> 5;
    const int warp_m = wid & 1;     // 2 warps over M (64 rows each)
    const int warp_n = wid >> 1;    // 4 warps over N (32 cols each)
    const int m0 = blockIdx.y << 7;
    const int n0 = blockIdx.x << 7;

    // Per-lane ldmatrix base offsets (bytes, within a stage)
    // A tile (16x8): matrices {r0-7,k0-3},{r8-15,k0-3},{r0-7,k4-7},{r8-15,k4-7}
    const uint32_t a_lane = (uint32_t)(((warp_m * 64 + (g & 1) * 8 + j) * GP
                                        + (g >> 1) * 4) * 4);
    // B pair (two 8-n tiles): matrices {ntA,k0-3},{ntA,k4-7},{ntB,k0-3},{ntB,k4-7}
    const uint32_t b_lane = (uint32_t)(((warp_n * 32 + (g >> 1) * 8 + j) * GP
                                        + (g & 1) * 4) * 4 + 128 * GP * 4);

    float acc[4][4][4];
#pragma unroll
    for (int i = 0; i < 4; i++)
#pragma unroll
        for (int jj = 0; jj < 4; jj++)
#pragma unroll
            for (int e = 0; e < 4; e++) acc[i][jj][e] = 0.f;

    const int nch = K / 32;
    const int grow = t >> 3;              // 0..31 (×4 via p)
    const int gc4  = (t & 7) << 2;        // 0..28

    float4 ra[4], rw[4];

#define LOAD_GMEM(cidx)                                                        \
    {                                                                          \
        const float* Ap = A + (size_t)m0 * K + (cidx) * 32;                    \
        const float* Wp = W + (size_t)n0 * K + (cidx) * 32;                    \
        _Pragma("unroll")                                                      \
        for (int p = 0; p < 4; p++) {                                          \
            int row = grow + p * 32;                                           \
            ra[p] = *(const float4*)(Ap + (size_t)row * K + gc4);              \
            rw[p] = *(const float4*)(Wp + (size_t)row * K + gc4);              \
        }                                                                      \
    }

#define STORE_STAGE(s)                                                         \
    {                                                                          \
        float* As = smf + (s) * GSTAGE_F;                                      \
        float* Bs = As + 128 * GP;                                             \
        _Pragma("unroll")                                                      \
        for (int p = 0; p < 4; p++) {                                          \
            int row = grow + p * 32;                                           \
            *(float4*)&As[row * GP + gc4] = ra[p];                             \
            *(float4*)&Bs[row * GP + gc4] = rw[p];                             \
        }                                                                      \
    }

    LOAD_GMEM(0);
    STORE_STAGE(0);
    __syncthreads();

    for (int c = 0; c < nch; c++) {
        const int s = c & 1;
        if (c + 1 < nch) LOAD_GMEM(c + 1);

        const uint32_t sbase = smb + (uint32_t)(s * GSTAGE_F * 4);
#pragma unroll
        for (int ks = 0; ks < 4; ks++) {
            uint32_t afr[4][4], bfr[4][2];
#pragma unroll
            for (int mt = 0; mt < 4; mt++)
                ldsm_x4(sbase + a_lane + (uint32_t)((mt * 16 * GP + ks * 8) * 4),
                        afr[mt]);
#pragma unroll
            for (int p = 0; p < 2; p++) {
                uint32_t q[4];
                ldsm_x4(sbase + b_lane + (uint32_t)((p * 16 * GP + ks * 8) * 4), q);
                bfr[2 * p][0] = q[0]; bfr[2 * p][1] = q[1];
                bfr[2 * p + 1][0] = q[2]; bfr[2 * p + 1][1] = q[3];
            }
#pragma unroll
            for (int mt = 0; mt < 4; mt++)
#pragma unroll
                for (int nt = 0; nt < 4; nt++)
                    mma_tf32(acc[mt][nt], afr[mt], bfr[nt]);
        }

        if (c + 1 < nch) STORE_STAGE(s ^ 1);   // opposite buffer: safe pre-sync
        __syncthreads();
    }

    // Epilogue: bias, optional tf32 rounding, direct stores
    const int c2 = cq << 1;
#pragma unroll
    for (int nt = 0; nt < 4; nt++) {
        const int gn = n0 + warp_n * 32 + nt * 8 + c2;
        const float b0 = bias[gn], b1 = bias[gn + 1];
#pragma unroll
        for (int mt = 0; mt < 4; mt++) {
            const int gm = m0 + warp_m * 64 + mt * 16 + r;
            float2 v0, v1;
            v0.x = acc[mt][nt][0] + b0; v0.y = acc[mt][nt][1] + b1;
            v1.x = acc[mt][nt][2] + b0; v1.y = acc[mt][nt][3] + b1;
            if (round_out) {
                v0.x = __uint_as_float(f2tf32(v0.x));
                v0.y = __uint_as_float(f2tf32(v0.y));
                v1.x = __uint_as_float(f2tf32(v1.x));
                v1.y = __uint_as_float(f2tf32(v1.y));
            }
            *(float2*)&Cout[(size_t)gm * Nt + gn]       = v0;
            *(float2*)&Cout[(size_t)(gm + 8) * Nt + gn] = v1;
        }
    }
#undef LOAD_GMEM
#undef STORE_STAGE
}

// ===========================================================================
// Flash attention: tf32 mma.sync, ldmatrix QK frags, k-perm PV register reuse.
// AQ=256, 512 threads = 16 warps x 16 query rows.
// Pitch 68 floats (272B; 272 mod 128 = 16 -> ldmatrix rows conflict-free;
// scalar V loads also conflict-free: bank = (4*row + col) mod 32 distinct).
// smem (floats): Qs[256][68] | K0 | V0 | K1 | V1 (64 rows each)
// ===========================================================================
#define AQ      256
#define AP      68
#define OFF_K0  (AQ * AP)
#define OFF_V0  (OFF_K0 + 64 * AP)
#define OFF_K1  (OFF_V0 + 64 * AP)
#define OFF_V1  (OFF_K1 + 64 * AP)
#define ATTN_SMEM ((OFF_V1 + 64 * AP) * 4)   // 139264 B

__global__ __launch_bounds__(512)
void attn_mma(const float* __restrict__ qkv, float* __restrict__ out)
{
    extern __shared__ float sm[];
    const uint32_t smb = smem_u32(sm);
    const int t    = threadIdx.x;
    const int lane = t & 31;
    const int wid  = t >> 5;
    const int r    = lane >> 2;
    const int cq   = lane & 3;
    const int g    = lane >> 3;
    const int j    = lane & 7;
    const int q0   = blockIdx.x * AQ;
    const int b    = blockIdx.y >> 4;
    const int h    = blockIdx.y & 15;
    const int rs   = 3 * C_DIM;

    const float* qb = qkv + ((size_t)(b * NSEQ + q0) * 3) * C_DIM + h * HDIM;
    const float* kb = qkv + ((size_t)(b * NSEQ) * 3 + 1) * C_DIM + h * HDIM;
    const float* vb = qkv + ((size_t)(b * NSEQ) * 3 + 2) * C_DIM + h * HDIM;

    const int wrow = wid * 16;   // warp's query-row base

    // ldmatrix lane offsets (bytes)
    const uint32_t q_lane = (uint32_t)(((wrow + (g & 1) * 8 + j) * AP
                                        + (g >> 1) * 4) * 4);
    const uint32_t k_lane = (uint32_t)((((g >> 1) * 8 + j) * AP
                                        + (g & 1) * 4) * 4);

    // ---- stage Q (pure copy; already tf32-rounded) ----
#pragma unroll
    for (int p = 0; p < 8; p++) {
        int fi  = t + 512 * p;
        int row = fi >> 4;
        int d4  = (fi & 15) << 2;
        *(float4*)&sm[row * AP + d4] = *(const float4*)(qb + (size_t)row * rs + d4);
    }

    const int krow0 = t >> 4;              // 0..31
    const int krow1 = krow0 + 32;
    const int kd4   = (t & 15) << 2;

    // ---- stage K/V tile 0 ----
    *(float4*)&sm[OFF_K0 + krow0 * AP + kd4] = *(const float4*)(kb + (size_t)krow0 * rs + kd4);
    *(float4*)&sm[OFF_K0 + krow1 * AP + kd4] = *(const float4*)(kb + (size_t)krow1 * rs + kd4);
    *(float4*)&sm[OFF_V0 + krow0 * AP + kd4] = *(const float4*)(vb + (size_t)krow0 * rs + kd4);
    *(float4*)&sm[OFF_V0 + krow1 * AP + kd4] = *(const float4*)(vb + (size_t)krow1 * rs + kd4);
    __syncthreads();

    float o_[8][4];
#pragma unroll
    for (int nt = 0; nt < 8; nt++)
#pragma unroll
        for (int e = 0; e < 4; e++) o_[nt][e] = 0.f;
    float m0r = -1e30f, m1r = -1e30f, l0r = 0.f, l1r = 0.f;

    for (int kt = 0; kt < NSEQ / 64; kt++) {
        const int s = kt & 1;
        const int koff = s ? OFF_K1 : OFF_K0;
        const int voff = s ? OFF_V1 : OFF_V0;
        const uint32_t kbase = smb + (uint32_t)(koff * 4);

        // ---- S = Q @ K^T (warp: 16 rows x 64 cols), ldmatrix frags ----
        float s_[8][4];
#pragma unroll
        for (int nt = 0; nt < 8; nt++)
#pragma unroll
            for (int e = 0; e < 4; e++) s_[nt][e] = 0.f;

#pragma unroll
        for (int ks = 0; ks < 8; ks++) {
            uint32_t a[4];
            ldsm_x4(smb + q_lane + (uint32_t)(ks * 32), a);
#pragma unroll
            for (int p = 0; p < 4; p++) {
                uint32_t qv[4];
                ldsm_x4(kbase + k_lane + (uint32_t)((p * 16 * AP) * 4 + ks * 32), qv);
                uint32_t b0[2] = {qv[0], qv[1]};
                uint32_t b1[2] = {qv[2], qv[3]};
                mma_tf32(s_[2 * p],     a, b0);
                mma_tf32(s_[2 * p + 1], a, b1);
            }
        }

        // ---- prefetch next K/V tile ----
        float4 pk0, pk1, pv0, pv1;
        if (kt + 1 < NSEQ / 64) {
            const float* kn = kb + (size_t)((kt + 1) * 64) * rs;
            const float* vn = vb + (size_t)((kt + 1) * 64) * rs;
            pk0 = *(const float4*)(kn + (size_t)krow0 * rs + kd4);
            pk1 = *(const float4*)(kn + (size_t)krow1 * rs + kd4);
            pv0 = *(const float4*)(vn + (size_t)krow0 * rs + kd4);
            pv1 = *(const float4*)(vn + (size_t)krow1 * rs + kd4);
        }

        // ---- online softmax (rows r, r+8; reduce over c-quad) ----
        float ml0 = -1e30f, ml1 = -1e30f;
#pragma unroll
        for (int nt = 0; nt < 8; nt++) {
            s_[nt][0] *= ATT_SCALE; s_[nt][1] *= ATT_SCALE;
            s_[nt][2] *= ATT_SCALE; s_[nt][3] *= ATT_SCALE;
            ml0 = fmaxf(ml0, fmaxf(s_[nt][0], s_[nt][1]));
            ml1 = fmaxf(ml1, fmaxf(s_[nt][2], s_[nt][3]));
        }
        ml0 = fmaxf(ml0, __shfl_xor_sync(0xffffffffu, ml0, 1));
        ml0 = fmaxf(ml0, __shfl_xor_sync(0xffffffffu, ml0, 2));
        ml1 = fmaxf(ml1, __shfl_xor_sync(0xffffffffu, ml1, 1));
        ml1 = fmaxf(ml1, __shfl_xor_sync(0xffffffffu, ml1, 2));

        float mn0 = fmaxf(m0r, ml0), mn1 = fmaxf(m1r, ml1);
        float cr0 = __expf(m0r - mn0), cr1 = __expf(m1r - mn1);
        m0r = mn0; m1r = mn1;

        float rs0 = 0.f, rs1 = 0.f;
#pragma unroll
        for (int nt = 0; nt < 8; nt++) {
            s_[nt][0] = __expf(s_[nt][0] - mn0);
            s_[nt][1] = __expf(s_[nt][1] - mn0);
            s_[nt][2] = __expf(s_[nt][2] - mn1);
            s_[nt][3] = __expf(s_[nt][3] - mn1);
            rs0 += s_[nt][0] + s_[nt][1];
            rs1 += s_[nt][2] + s_[nt][3];
        }
        rs0 += __shfl_xor_sync(0xffffffffu, rs0, 1);
        rs0 += __shfl_xor_sync(0xffffffffu, rs0, 2);
        rs1 += __shfl_xor_sync(0xffffffffu, rs1, 1);
        rs1 += __shfl_xor_sync(0xffffffffu, rs1, 2);
        l0r = l0r * cr0 + rs0;
        l1r = l1r * cr1 + rs1;

#pragma unroll
        for (int nt = 0; nt < 8; nt++) {
            o_[nt][0] *= cr0; o_[nt][1] *= cr0;
            o_[nt][2] *= cr1; o_[nt][3] *= cr1;
        }

        // ---- O += P @ V : P straight from s_ registers (k-perm) ----
        //   a0 = P[r][ks*8+2cq]   = s_[ks][0]
        //   a1 = P[r+8][ks*8+2cq] = s_[ks][2]
        //   a2 = P[r][ks*8+2cq+1] = s_[ks][1]
        //   a3 = P[r+8][ks*8+2cq+1] = s_[ks][3]
        // V b-frags: physical key rows ks*8+2cq, +1 at col nt*8+r.
#pragma unroll
        for (int ks = 0; ks < 8; ks++) {
            uint32_t a[4];
            a[0] = f2tf32(s_[ks][0]);
            a[1] = f2tf32(s_[ks][2]);
            a[2] = f2tf32(s_[ks][1]);
            a[3] = f2tf32(s_[ks][3]);
            const float* Vb = &sm[voff + (ks * 8 + 2 * cq) * AP + r];
#pragma unroll
            for (int nt = 0; nt < 8; nt++) {
                uint32_t bf[2];
                bf[0] = __float_as_uint(Vb[nt * 8]);
                bf[1] = __float_as_uint(Vb[nt * 8 + AP]);
                mma_tf32(o_[nt], a, bf);
            }
        }

        // ---- stage next tile into opposite buffer, then one barrier ----
        if (kt + 1 < NSEQ / 64) {
            const int nk = s ? OFF_K0 : OFF_K1;
            const int nv = s ? OFF_V0 : OFF_V1;
            *(float4*)&sm[nk + krow0 * AP + kd4] = pk0;
            *(float4*)&sm[nk + krow1 * AP + kd4] = pk1;
            *(float4*)&sm[nv + krow0 * AP + kd4] = pv0;
            *(float4*)&sm[nv + krow1 * AP + kd4] = pv1;
        }
        __syncthreads();
    }

    // ---- epilogue: normalize, round to tf32 (feeds proj gemm), store ----
    const float i0 = 1.f / l0r, i1 = 1.f / l1r;
#pragma unroll
    for (int nt = 0; nt < 8; nt++) {
        const int col = h * HDIM + nt * 8 + 2 * cq;
        float2 v0, v1;
        v0.x = __uint_as_float(f2tf32(o_[nt][0] * i0));
        v0.y = __uint_as_float(f2tf32(o_[nt][1] * i0));
        v1.x = __uint_as_float(f2tf32(o_[nt][2] * i1));
        v1.y = __uint_as_float(f2tf32(o_[nt][3] * i1));
        *(float2*)&out[(size_t)(b * NSEQ + q0 + wrow + r) * C_DIM + col]     = v0;
        *(float2*)&out[(size_t)(b * NSEQ + q0 + wrow + r + 8) * C_DIM + col] = v1;
    }
}

// ---------------------------------------------------------------------------
extern "C" void kernel_launch(void* const* d_in, const int* in_sizes, int n_in,
                              void* d_out, int out_size)
{
    const float* x      = (const float*)d_in[0];
    const float* w_qkv  = (const float*)d_in[1];
    const float* b_qkv  = (const float*)d_in[2];
    const float* w_proj = (const float*)d_in[3];
    const float* b_proj = (const float*)d_in[4];
    float* out = (float*)d_out;

    float *qkv_s, *att_s, *xtf, *wqtf, *wptf;
    cudaGetSymbolAddress((void**)&qkv_s, g_qkv);
    cudaGetSymbolAddress((void**)&att_s, g_att);
    cudaGetSymbolAddress((void**)&xtf,   g_xtf);
    cudaGetSymbolAddress((void**)&wqtf,  g_wqkv_tf);
    cudaGetSymbolAddress((void**)&wptf,  g_wproj_tf);

    cudaFuncSetAttribute(gemm_mma_tf32, cudaFuncAttributeMaxDynamicSharedMemorySize, GEMM_SMEM);
    cudaFuncSetAttribute(attn_mma, cudaFuncAttributeMaxDynamicSharedMemorySize, ATTN_SMEM);

    // 0) Pre-round inputs to tf32 (hoists all cvt out of GEMM/attention loops)
    cvt_tf32_pass<<<592, 256>>>(x,      xtf,  ROWS * C_DIM / 4);
    cvt_tf32_pass<<<592, 256>>>(w_qkv,  wqtf, 3 * C_DIM * C_DIM / 4);
    cvt_tf32_pass<<<592, 256>>>(w_proj, wptf, C_DIM * C_DIM / 4);

    // 1) QKV projection -> tf32-rounded [4096,3072]
    dim3 g1(3 * C_DIM / 128, ROWS / 128);
    gemm_mma_tf32<<<g1, 256, GEMM_SMEM>>>(xtf, wqtf, b_qkv, qkv_s,
                                          ROWS, 3 * C_DIM, C_DIM, 1);

    // 2) Fused attention -> tf32-rounded [4096,1024]
    dim3 g2(NSEQ / AQ, BATCH * NHEADS);
    attn_mma<<<g2, 512, ATTN_SMEM>>>(qkv_s, att_s);

    // 3) Output projection -> fp32 out
    dim3 g3(C_DIM / 128, ROWS / 128);
    gemm_mma_tf32<<<g3, 256, GEMM_SMEM>>>(att_s, wptf, b_proj, out,
                                          ROWS, C_DIM, C_DIM, 0);
}

// round 9
// speedup vs baseline: 1.4240x; 1.1080x over previous
#include <cuda_runtime.h>
#include <cstdint>

#define C_DIM   1024
#define NSEQ    2048
#define NHEADS  16
#define HDIM    64
#define BATCH   2
#define ROWS    (BATCH * NSEQ)       // 4096
#define ATT_SCALE 0.125f             // 1/sqrt(64)

// Scratch (no allocations allowed in kernel_launch)
__device__ float g_qkv[ROWS * 3 * C_DIM];       // [4096, 3072] (tf32-rounded)
__device__ float g_att[ROWS * C_DIM];           // [4096, 1024] (tf32-rounded)
__device__ float g_xtf[ROWS * C_DIM];           // x, tf32-rounded
__device__ float g_wqkv_tf[3 * C_DIM * C_DIM];  // w_qkv, tf32-rounded
__device__ float g_wproj_tf[C_DIM * C_DIM];     // w_proj, tf32-rounded

// ===========================================================================
// helpers (arch-independent PTX)
// ===========================================================================
__device__ __forceinline__ uint32_t f2tf32(float x) {
    uint32_t r;
    asm("cvt.rna.tf32.f32 %0, %1;" : "=r"(r) : "f"(x));
    return r;
}
__device__ __forceinline__ uint32_t smem_u32(const void* p) {
    uint32_t a;
    asm("{ .reg .u64 t; cvta.to.shared.u64 t, %1; cvt.u32.u64 %0, t; }"
        : "=r"(a) : "l"(p));
    return a;
}
__device__ __forceinline__ void ldsm_x4(uint32_t addr, uint32_t* d) {
    asm volatile("ldmatrix.sync.aligned.m8n8.x4.shared.b16 {%0,%1,%2,%3}, [%4];"
                 : "=r"(d[0]), "=r"(d[1]), "=r"(d[2]), "=r"(d[3]) : "r"(addr));
}
__device__ __forceinline__ void mma_tf32(float* d, const uint32_t* a, const uint32_t* b) {
    asm volatile(
        "mma.sync.aligned.m16n8k8.row.col.f32.tf32.tf32.f32 "
        "{%0,%1,%2,%3}, {%4,%5,%6,%7}, {%8,%9}, {%0,%1,%2,%3};"
        : "+f"(d[0]), "+f"(d[1]), "+f"(d[2]), "+f"(d[3])
        : "r"(a[0]), "r"(a[1]), "r"(a[2]), "r"(a[3]), "r"(b[0]), "r"(b[1]));
}
#define CP16(dst, src) \
    asm volatile("cp.async.cg.shared.global [%0], [%1], 16;" \
                 :: "r"(dst), "l"(src) : "memory")
#define CP_COMMIT() asm volatile("cp.async.commit_group;" ::: "memory")
#define CP_WAIT1()  asm volatile("cp.async.wait_group 1;" ::: "memory")
#define CP_WAIT0()  asm volatile("cp.async.wait_group 0;" ::: "memory")

// ===========================================================================
// Merged pre-pass: round three arrays fp32 -> tf32-in-fp32 (rna).
// ===========================================================================
__global__ void cvt3_tf32(const float* a, float* oa, int na4,
                          const float* b, float* ob, int nb4,
                          const float* c, float* oc, int nc4)
{
    int i = blockIdx.x * blockDim.x + threadIdx.x;
    int stride = gridDim.x * blockDim.x;
    int tot = na4 + nb4 + nc4;
    for (; i < tot; i += stride) {
        const float4* src;
        uint4* dst;
        int k = i;
        if (k < na4) { src = (const float4*)a + k; dst = (uint4*)oa + k; }
        else if ((k -= na4) < nb4) { src = (const float4*)b + k; dst = (uint4*)ob + k; }
        else { k -= nb4; src = (const float4*)c + k; dst = (uint4*)oc + k; }
        float4 v = *src;
        *dst = make_uint4(f2tf32(v.x), f2tf32(v.y), f2tf32(v.z), f2tf32(v.w));
    }
}

// ===========================================================================
// tf32 mma.sync NT GEMM, cp.async 3-stage pipeline:
// C[M,Nt] = A[M,K] @ W[Nt,K]^T + bias[Nt].  Inputs pre-rounded tf32.
// 128x128 tile, BK=32, 256 threads (8 warps, 64x32), 2 CTAs/SM.
// Pitch 36 floats; ldmatrix fragment loads.
// ===========================================================================
#define GP 36
#define GSTG (2 * 128 * GP)              // floats per stage (A+B)
#define GEMM_SMEM (3 * GSTG * 4)         // 110592 B -> 2 CTAs/SM

__global__ __launch_bounds__(256, 2)
void gemm_mma_tf32(const float* __restrict__ A, const float* __restrict__ W,
                   const float* __restrict__ bias, float* __restrict__ Cout,
                   int M, int Nt, int K, int round_out)
{
    extern __shared__ float smf[];
    const uint32_t smb = smem_u32(smf);
    const int t      = threadIdx.x;
    const int lane   = t & 31;
    const int r      = lane >> 2;
    const int cq     = lane & 3;
    const int g      = lane >> 3;
    const int j      = lane & 7;
    const int wid    = t >> 5;
    const int warp_m = wid & 1;
    const int warp_n = wid >> 1;
    const int m0 = blockIdx.y << 7;
    const int n0 = blockIdx.x << 7;

    const uint32_t a_lane = (uint32_t)(((warp_m * 64 + (g & 1) * 8 + j) * GP
                                        + (g >> 1) * 4) * 4);
    const uint32_t b_lane = (uint32_t)(((warp_n * 32 + (g >> 1) * 8 + j) * GP
                                        + (g & 1) * 4) * 4 + 128 * GP * 4);

    const int grow = t >> 3;              // 0..31 (x4 via p)
    const int gc4  = (t & 7) << 2;        // 0..28

    // cp.async issue of one BK=32 chunk into stage s
#define ISSUE_CHUNK(cidx, s)                                                   \
    {                                                                          \
        const float* Ap = A + (size_t)m0 * K + (cidx) * 32;                    \
        const float* Wp = W + (size_t)n0 * K + (cidx) * 32;                    \
        const uint32_t sb = smb + (uint32_t)((s) * GSTG * 4);                  \
        _Pragma("unroll")                                                      \
        for (int p = 0; p < 4; p++) {                                          \
            int row = grow + p * 32;                                           \
            CP16(sb + (uint32_t)((row * GP + gc4) * 4),                        \
                 Ap + (size_t)row * K + gc4);                                  \
            CP16(sb + (uint32_t)((128 * GP + row * GP + gc4) * 4),             \
                 Wp + (size_t)row * K + gc4);                                  \
        }                                                                      \
        CP_COMMIT();                                                           \
    }

    float acc[4][4][4];
#pragma unroll
    for (int i = 0; i < 4; i++)
#pragma unroll
        for (int jj = 0; jj < 4; jj++)
#pragma unroll
            for (int e = 0; e < 4; e++) acc[i][jj][e] = 0.f;

    const int nch = K / 32;
    ISSUE_CHUNK(0, 0);
    ISSUE_CHUNK(1, 1);

    int stage = 0;
    for (int c = 0; c < nch; c++) {
        if (c + 1 < nch) CP_WAIT1(); else CP_WAIT0();
        __syncthreads();
        if (c + 2 < nch) {
            int ns = stage + 2; if (ns >= 3) ns -= 3;
            ISSUE_CHUNK(c + 2, ns);
        }

        const uint32_t sbase = smb + (uint32_t)(stage * GSTG * 4);
#pragma unroll
        for (int ks = 0; ks < 4; ks++) {
            uint32_t afr[4][4], bfr[4][2];
#pragma unroll
            for (int mt = 0; mt < 4; mt++)
                ldsm_x4(sbase + a_lane + (uint32_t)((mt * 16 * GP + ks * 8) * 4),
                        afr[mt]);
#pragma unroll
            for (int p = 0; p < 2; p++) {
                uint32_t q[4];
                ldsm_x4(sbase + b_lane + (uint32_t)((p * 16 * GP + ks * 8) * 4), q);
                bfr[2 * p][0] = q[0]; bfr[2 * p][1] = q[1];
                bfr[2 * p + 1][0] = q[2]; bfr[2 * p + 1][1] = q[3];
            }
#pragma unroll
            for (int mt = 0; mt < 4; mt++)
#pragma unroll
                for (int nt = 0; nt < 4; nt++)
                    mma_tf32(acc[mt][nt], afr[mt], bfr[nt]);
        }
        if (++stage == 3) stage = 0;
        __syncthreads();
    }

    // Epilogue: bias, optional tf32 rounding, direct stores
    const int c2 = cq << 1;
#pragma unroll
    for (int nt = 0; nt < 4; nt++) {
        const int gn = n0 + warp_n * 32 + nt * 8 + c2;
        const float b0 = bias[gn], b1 = bias[gn + 1];
#pragma unroll
        for (int mt = 0; mt < 4; mt++) {
            const int gm = m0 + warp_m * 64 + mt * 16 + r;
            float2 v0, v1;
            v0.x = acc[mt][nt][0] + b0; v0.y = acc[mt][nt][1] + b1;
            v1.x = acc[mt][nt][2] + b0; v1.y = acc[mt][nt][3] + b1;
            if (round_out) {
                v0.x = __uint_as_float(f2tf32(v0.x));
                v0.y = __uint_as_float(f2tf32(v0.y));
                v1.x = __uint_as_float(f2tf32(v1.x));
                v1.y = __uint_as_float(f2tf32(v1.y));
            }
            *(float2*)&Cout[(size_t)gm * Nt + gn]       = v0;
            *(float2*)&Cout[(size_t)(gm + 8) * Nt + gn] = v1;
        }
    }
#undef ISSUE_CHUNK
}

// ===========================================================================
// Flash attention: tf32 mma.sync, 32-query warps (amortizes K/V fragment
// wavefronts over 2x HMMA -> smem no longer binding), cp.async 3-stage K/V
// ring, ldmatrix Q/K frags, k-perm PV register reuse (P never in smem).
// AQ=256, 256 threads = 8 warps x 32 query rows. Pitch 68.
// ===========================================================================
#define AQ      256
#define AP      68
#define KSTG    (2 * 64 * AP)                 // K+V one stage (floats)
#define OFF_KV  (AQ * AP)
#define ATTN_SMEM ((AQ * AP + 3 * KSTG) * 4)  // 174080 B

__global__ __launch_bounds__(256, 1)
void attn_mma(const float* __restrict__ qkv, float* __restrict__ out)
{
    extern __shared__ float sm[];
    const uint32_t smb = smem_u32(sm);
    const int t    = threadIdx.x;
    const int lane = t & 31;
    const int wid  = t >> 5;
    const int r    = lane >> 2;
    const int cq   = lane & 3;
    const int g    = lane >> 3;
    const int j    = lane & 7;
    const int q0   = blockIdx.x * AQ;
    const int b    = blockIdx.y >> 4;
    const int h    = blockIdx.y & 15;
    const int rs   = 3 * C_DIM;

    const float* qb = qkv + ((size_t)(b * NSEQ + q0) * 3) * C_DIM + h * HDIM;
    const float* kb = qkv + ((size_t)(b * NSEQ) * 3 + 1) * C_DIM + h * HDIM;
    const float* vb = qkv + ((size_t)(b * NSEQ) * 3 + 2) * C_DIM + h * HDIM;

    const int wrow = wid * 32;   // warp's query-row base (32 rows)

    const uint32_t q_lane = (uint32_t)(((wrow + (g & 1) * 8 + j) * AP
                                        + (g >> 1) * 4) * 4);
    const uint32_t k_lane = (uint32_t)((((g >> 1) * 8 + j) * AP
                                        + (g & 1) * 4) * 4);

    const int srow = t >> 4;              // 0..15 (x4 via p)
    const int sd4  = (t & 15) << 2;

    // ---- Q via cp.async (group 0) ----
#pragma unroll
    for (int p = 0; p < 16; p++) {
        int row = srow + p * 16;
        CP16(smb + (uint32_t)((row * AP + sd4) * 4), qb + (size_t)row * rs + sd4);
    }
    CP_COMMIT();

    // K/V tile issue into stage s (groups 1,2,... in order)
#define ISSUE_KV(kt, s)                                                        \
    {                                                                          \
        const float* kn = kb + (size_t)((kt) * 64) * rs;                       \
        const float* vn = vb + (size_t)((kt) * 64) * rs;                       \
        const uint32_t sb = smb + (uint32_t)((OFF_KV + (s) * KSTG) * 4);       \
        _Pragma("unroll")                                                      \
        for (int p = 0; p < 4; p++) {                                          \
            int row = srow + p * 16;                                           \
            CP16(sb + (uint32_t)((row * AP + sd4) * 4),                        \
                 kn + (size_t)row * rs + sd4);                                 \
            CP16(sb + (uint32_t)((64 * AP + row * AP + sd4) * 4),              \
                 vn + (size_t)row * rs + sd4);                                 \
        }                                                                      \
        CP_COMMIT();                                                           \
    }

    ISSUE_KV(0, 0);
    ISSUE_KV(1, 1);

    float o_[2][8][4];
#pragma unroll
    for (int mt = 0; mt < 2; mt++)
#pragma unroll
        for (int nt = 0; nt < 8; nt++)
#pragma unroll
            for (int e = 0; e < 4; e++) o_[mt][nt][e] = 0.f;
    float m_r[2][2], l_r[2][2];
#pragma unroll
    for (int mt = 0; mt < 2; mt++) {
        m_r[mt][0] = -1e30f; m_r[mt][1] = -1e30f;
        l_r[mt][0] = 0.f;    l_r[mt][1] = 0.f;
    }

    const int NT = NSEQ / 64;
    int stage = 0;
    for (int kt = 0; kt < NT; kt++) {
        if (kt + 1 < NT) CP_WAIT1(); else CP_WAIT0();
        __syncthreads();
        if (kt + 2 < NT) {
            int ns = stage + 2; if (ns >= 3) ns -= 3;
            ISSUE_KV(kt + 2, ns);
        }

        const uint32_t kbase = smb + (uint32_t)((OFF_KV + stage * KSTG) * 4);
        const float*   Vst   = &sm[OFF_KV + stage * KSTG + 64 * AP];

        // ---- S = Q @ K^T (warp: 32 rows x 64 cols) ----
        float s_[2][8][4];
#pragma unroll
        for (int mt = 0; mt < 2; mt++)
#pragma unroll
            for (int nt = 0; nt < 8; nt++)
#pragma unroll
                for (int e = 0; e < 4; e++) s_[mt][nt][e] = 0.f;

#pragma unroll
        for (int ks = 0; ks < 8; ks++) {
            uint32_t aq[2][4];
            ldsm_x4(smb + q_lane + (uint32_t)(ks * 32), aq[0]);
            ldsm_x4(smb + q_lane + (uint32_t)(16 * AP * 4 + ks * 32), aq[1]);
#pragma unroll
            for (int p = 0; p < 4; p++) {
                uint32_t qv[4];
                ldsm_x4(kbase + k_lane + (uint32_t)((p * 16 * AP) * 4 + ks * 32), qv);
                uint32_t b0[2] = {qv[0], qv[1]};
                uint32_t b1[2] = {qv[2], qv[3]};
                mma_tf32(s_[0][2 * p],     aq[0], b0);
                mma_tf32(s_[0][2 * p + 1], aq[0], b1);
                mma_tf32(s_[1][2 * p],     aq[1], b0);
                mma_tf32(s_[1][2 * p + 1], aq[1], b1);
            }
        }

        // ---- online softmax (per mt: rows r and r+8; reduce over c-quad) ----
#pragma unroll
        for (int mt = 0; mt < 2; mt++) {
            float ml0 = -1e30f, ml1 = -1e30f;
#pragma unroll
            for (int nt = 0; nt < 8; nt++) {
                s_[mt][nt][0] *= ATT_SCALE; s_[mt][nt][1] *= ATT_SCALE;
                s_[mt][nt][2] *= ATT_SCALE; s_[mt][nt][3] *= ATT_SCALE;
                ml0 = fmaxf(ml0, fmaxf(s_[mt][nt][0], s_[mt][nt][1]));
                ml1 = fmaxf(ml1, fmaxf(s_[mt][nt][2], s_[mt][nt][3]));
            }
            ml0 = fmaxf(ml0, __shfl_xor_sync(0xffffffffu, ml0, 1));
            ml0 = fmaxf(ml0, __shfl_xor_sync(0xffffffffu, ml0, 2));
            ml1 = fmaxf(ml1, __shfl_xor_sync(0xffffffffu, ml1, 1));
            ml1 = fmaxf(ml1, __shfl_xor_sync(0xffffffffu, ml1, 2));

            float mn0 = fmaxf(m_r[mt][0], ml0), mn1 = fmaxf(m_r[mt][1], ml1);
            float cr0 = __expf(m_r[mt][0] - mn0), cr1 = __expf(m_r[mt][1] - mn1);
            m_r[mt][0] = mn0; m_r[mt][1] = mn1;

            float rs0 = 0.f, rs1 = 0.f;
#pragma unroll
            for (int nt = 0; nt < 8; nt++) {
                s_[mt][nt][0] = __expf(s_[mt][nt][0] - mn0);
                s_[mt][nt][1] = __expf(s_[mt][nt][1] - mn0);
                s_[mt][nt][2] = __expf(s_[mt][nt][2] - mn1);
                s_[mt][nt][3] = __expf(s_[mt][nt][3] - mn1);
                rs0 += s_[mt][nt][0] + s_[mt][nt][1];
                rs1 += s_[mt][nt][2] + s_[mt][nt][3];
            }
            rs0 += __shfl_xor_sync(0xffffffffu, rs0, 1);
            rs0 += __shfl_xor_sync(0xffffffffu, rs0, 2);
            rs1 += __shfl_xor_sync(0xffffffffu, rs1, 1);
            rs1 += __shfl_xor_sync(0xffffffffu, rs1, 2);
            l_r[mt][0] = l_r[mt][0] * cr0 + rs0;
            l_r[mt][1] = l_r[mt][1] * cr1 + rs1;

#pragma unroll
            for (int nt = 0; nt < 8; nt++) {
                o_[mt][nt][0] *= cr0; o_[mt][nt][1] *= cr0;
                o_[mt][nt][2] *= cr1; o_[mt][nt][3] *= cr1;
            }
        }

        // ---- O += P @ V : P straight from s_ registers (k-perm); V-frags
        //      shared across both mt ----
#pragma unroll
        for (int ks = 0; ks < 8; ks++) {
            uint32_t a0[4], a1[4];
            a0[0] = f2tf32(s_[0][ks][0]); a0[1] = f2tf32(s_[0][ks][2]);
            a0[2] = f2tf32(s_[0][ks][1]); a0[3] = f2tf32(s_[0][ks][3]);
            a1[0] = f2tf32(s_[1][ks][0]); a1[1] = f2tf32(s_[1][ks][2]);
            a1[2] = f2tf32(s_[1][ks][1]); a1[3] = f2tf32(s_[1][ks][3]);
            const float* Vb = Vst + (ks * 8 + 2 * cq) * AP + r;
#pragma unroll
            for (int nt = 0; nt < 8; nt++) {
                uint32_t bf[2];
                bf[0] = __float_as_uint(Vb[nt * 8]);
                bf[1] = __float_as_uint(Vb[nt * 8 + AP]);
                mma_tf32(o_[0][nt], a0, bf);
                mma_tf32(o_[1][nt], a1, bf);
            }
        }

        if (++stage == 3) stage = 0;
        __syncthreads();
    }

    // ---- epilogue: normalize, round to tf32 (feeds proj gemm), store ----
#pragma unroll
    for (int mt = 0; mt < 2; mt++) {
        const float i0 = 1.f / l_r[mt][0], i1 = 1.f / l_r[mt][1];
        const int row0 = b * NSEQ + q0 + wrow + mt * 16 + r;
#pragma unroll
        for (int nt = 0; nt < 8; nt++) {
            const int col = h * HDIM + nt * 8 + 2 * cq;
            float2 v0, v1;
            v0.x = __uint_as_float(f2tf32(o_[mt][nt][0] * i0));
            v0.y = __uint_as_float(f2tf32(o_[mt][nt][1] * i0));
            v1.x = __uint_as_float(f2tf32(o_[mt][nt][2] * i1));
            v1.y = __uint_as_float(f2tf32(o_[mt][nt][3] * i1));
            *(float2*)&out[(size_t)row0 * C_DIM + col]       = v0;
            *(float2*)&out[(size_t)(row0 + 8) * C_DIM + col] = v1;
        }
    }
#undef ISSUE_KV
}

// ---------------------------------------------------------------------------
extern "C" void kernel_launch(void* const* d_in, const int* in_sizes, int n_in,
                              void* d_out, int out_size)
{
    const float* x      = (const float*)d_in[0];
    const float* w_qkv  = (const float*)d_in[1];
    const float* b_qkv  = (const float*)d_in[2];
    const float* w_proj = (const float*)d_in[3];
    const float* b_proj = (const float*)d_in[4];
    float* out = (float*)d_out;

    float *qkv_s, *att_s, *xtf, *wqtf, *wptf;
    cudaGetSymbolAddress((void**)&qkv_s, g_qkv);
    cudaGetSymbolAddress((void**)&att_s, g_att);
    cudaGetSymbolAddress((void**)&xtf,   g_xtf);
    cudaGetSymbolAddress((void**)&wqtf,  g_wqkv_tf);
    cudaGetSymbolAddress((void**)&wptf,  g_wproj_tf);

    cudaFuncSetAttribute(gemm_mma_tf32, cudaFuncAttributeMaxDynamicSharedMemorySize, GEMM_SMEM);
    cudaFuncSetAttribute(attn_mma, cudaFuncAttributeMaxDynamicSharedMemorySize, ATTN_SMEM);

    // 0) Pre-round inputs to tf32 (single merged launch)
    cvt3_tf32<<<1184, 256>>>(x, xtf, ROWS * C_DIM / 4,
                             w_qkv, wqtf, 3 * C_DIM * C_DIM / 4,
                             w_proj, wptf, C_DIM * C_DIM / 4);

    // 1) QKV projection -> tf32-rounded [4096,3072]
    dim3 g1(3 * C_DIM / 128, ROWS / 128);
    gemm_mma_tf32<<<g1, 256, GEMM_SMEM>>>(xtf, wqtf, b_qkv, qkv_s,
                                          ROWS, 3 * C_DIM, C_DIM, 1);

    // 2) Fused attention -> tf32-rounded [4096,1024]
    dim3 g2(NSEQ / AQ, BATCH * NHEADS);
    attn_mma<<<g2, 256, ATTN_SMEM>>>(qkv_s, att_s);

    // 3) Output projection -> fp32 out
    dim3 g3(C_DIM / 128, ROWS / 128);
    gemm_mma_tf32<<<g3, 256, GEMM_SMEM>>>(att_s, wptf, b_proj, out,
                                          ROWS, C_DIM, C_DIM, 0);
}